// round 3
// baseline (speedup 1.0000x reference)
#include <cuda_runtime.h>
#include <math.h>
#include <stdint.h>

// Problem constants (fixed shapes from reference setup_inputs)
#define Bc   2
#define Nn   8192
#define Ff   128
#define Ee   131072
#define Hh   256
#define NHh  4
#define Dd   64
#define FEATN 268
#define BE   (Bc*Ee)     // 262144 edge rows
#define BNr  (Bc*Nn)     // 16384 node rows

// ---------------- static scratch (no allocations allowed) ----------------
static __device__ float g_feat[BE * FEATN];      // gathered edge features (268)
static __device__ float g_mid[BE * Hh];          // hmid concat / reused for coord-MLP hidden
static __device__ float g_ef[BE * Hh];           // combined -> layernormed edge_feat
static __device__ float g_cdiff[BE * 3];
static __device__ float g_wsc[BE];               // per-edge scalar w
static __device__ float g_agg[BNr * Hh];         // segment-sum of edge_feat
static __device__ float g_nodein[BNr * (Hh + Ff)];
static __device__ float g_nodemid[BNr * Hh];
static __device__ float g_w1cat[FEATN * Hh];     // w1 transposed to (FEAT, NH*D)

// ---------------- small helper kernels ----------------

// w1cat[f*256 + h*64 + d] = w1[h][f][d]
__global__ void k_w1cat(const float* __restrict__ w1) {
    int idx = blockIdx.x * blockDim.x + threadIdx.x;
    if (idx >= FEATN * Hh) return;
    int f = idx >> 8;        // /256
    int c = idx & 255;
    int h = c >> 6, d = c & 63;
    g_w1cat[idx] = w1[((h * FEATN) + f) * Dd + d];
}

// One warp per edge row: gather h[row], h[col], compute geometry features
__global__ void k_edge(const float* __restrict__ h, const float* __restrict__ coord,
                       const int* __restrict__ ei) {
    int wid = blockIdx.x * (blockDim.x >> 5) + (threadIdx.x >> 5);
    int lane = threadIdx.x & 31;
    if (wid >= BE) return;
    int b = wid / Ee, j = wid - b * Ee;
    int i = ei[j], k = ei[Ee + j];
    float* feat = g_feat + (size_t)wid * FEATN;
    const float4* hi4 = (const float4*)(h + ((size_t)b * Nn + i) * Ff);
    const float4* hk4 = (const float4*)(h + ((size_t)b * Nn + k) * Ff);
    ((float4*)feat)[lane]      = hi4[lane];
    ((float4*)feat)[32 + lane] = hk4[lane];
    if (lane == 0) {
        const float* ci = coord + ((size_t)b * Nn + i) * 3;
        const float* ck = coord + ((size_t)b * Nn + k) * 3;
        float cix = ci[0], ciy = ci[1], ciz = ci[2];
        float ckx = ck[0], cky = ck[1], ckz = ck[2];
        float dx = cix - ckx, dy = ciy - cky, dz = ciz - ckz;
        float radial = dx * dx + dy * dy + dz * dz;
        float dist = sqrtf(radial);
        float dotv = cix * ckx + ciy * cky + ciz * ckz;
        float inva = 1.f / (dist + 1e-8f);
        float ax = dx * inva, ay = dy * inva, az = dz * inva;
        float crx = ciy * ckz - ciz * cky;
        float cry = ciz * ckx - cix * ckz;
        float crz = cix * cky - ciy * ckx;
        float nb = sqrtf(crx * crx + cry * cry + crz * crz);
        float invb = 1.f / (nb + 1e-8f);
        float bx = crx * invb, by = cry * invb, bz = crz * invb;
        float cx = ay * bz - az * by;
        float cy = az * bx - ax * bz;
        float cz = ax * by - ay * bx;
        float na  = sqrtf(ax * ax + ay * ay + az * az);
        float nbv = sqrtf(bx * bx + by * by + bz * bz);
        float ncv = sqrtf(cx * cx + cy * cy + cz * cz);
        bool bad = (na < 1e-6f) || (nbv < 1e-6f) || (ncv < 1e-6f);
        if (bad) { ax = 1.f; bx = 0.f; cx = 0.f;
                   ay = 0.f; by = 1.f; cy = 0.f;
                   az = 0.f; bz = 0.f; cz = 1.f; }
        feat[256] = radial; feat[257] = dist; feat[258] = dotv;
        feat[259] = ax; feat[260] = bx; feat[261] = cx;
        feat[262] = ay; feat[263] = by; feat[264] = cy;
        feat[265] = az; feat[266] = bz; feat[267] = cz;
        g_cdiff[wid * 3 + 0] = dx;
        g_cdiff[wid * 3 + 1] = dy;
        g_cdiff[wid * 3 + 2] = dz;
    }
}

// ---------------- generic fp32 tiled GEMM: C = A(MxK) * B(KxN) [+bias][silu][+resid]
// EPI: 0 none, 1 bias, 2 bias+silu, 3 bias+residual
template <int EPI>
__global__ void __launch_bounds__(256) k_gemm(
    const float* __restrict__ A, const float* __restrict__ B, float* __restrict__ C,
    int M, int N, int K, int lda, int ldb, int ldc,
    const float* __restrict__ bias, const float* __restrict__ resid, int ldr)
{
    __shared__ float As[16][64];
    __shared__ float Bs[16][64];
    const int tid = threadIdx.x;
    const int tx = tid & 15, ty = tid >> 4;
    const int m0 = blockIdx.y * 64, n0 = blockIdx.x * 64;
    const int arow = tid >> 2, acol = (tid & 3) << 2;
    const int brow = tid >> 4, bcol = (tid & 15) << 2;

    float acc[4][4];
#pragma unroll
    for (int i = 0; i < 4; i++)
#pragma unroll
        for (int j = 0; j < 4; j++) acc[i][j] = 0.f;

    const float* Aptr = A + (size_t)(m0 + arow) * lda;
    for (int k0 = 0; k0 < K; k0 += 16) {
        float4 av;
        int ka = k0 + acol;
        if (ka + 3 < K) {
            av = *(const float4*)(Aptr + ka);
        } else {
            av.x = (ka     < K) ? Aptr[ka]     : 0.f;
            av.y = (ka + 1 < K) ? Aptr[ka + 1] : 0.f;
            av.z = (ka + 2 < K) ? Aptr[ka + 2] : 0.f;
            av.w = (ka + 3 < K) ? Aptr[ka + 3] : 0.f;
        }
        float4 bv = make_float4(0.f, 0.f, 0.f, 0.f);
        if (k0 + brow < K)
            bv = *(const float4*)(B + (size_t)(k0 + brow) * ldb + n0 + bcol);

        As[acol + 0][arow] = av.x;
        As[acol + 1][arow] = av.y;
        As[acol + 2][arow] = av.z;
        As[acol + 3][arow] = av.w;
        *(float4*)&Bs[brow][bcol] = bv;
        __syncthreads();
#pragma unroll
        for (int kk = 0; kk < 16; kk++) {
            float4 a = *(const float4*)&As[kk][ty << 2];
            float4 b = *(const float4*)&Bs[kk][tx << 2];
            float ar[4] = {a.x, a.y, a.z, a.w};
            float br[4] = {b.x, b.y, b.z, b.w};
#pragma unroll
            for (int i = 0; i < 4; i++)
#pragma unroll
                for (int j = 0; j < 4; j++) acc[i][j] += ar[i] * br[j];
        }
        __syncthreads();
    }

    int col = n0 + (tx << 2);
    float4 bb = make_float4(0.f, 0.f, 0.f, 0.f);
    if (EPI >= 1) bb = *(const float4*)(bias + col);
#pragma unroll
    for (int i = 0; i < 4; i++) {
        int row = m0 + (ty << 2) + i;
        float4 v = make_float4(acc[i][0], acc[i][1], acc[i][2], acc[i][3]);
        if (EPI >= 1) { v.x += bb.x; v.y += bb.y; v.z += bb.z; v.w += bb.w; }
        if (EPI == 2) {
            v.x = v.x / (1.f + expf(-v.x));
            v.y = v.y / (1.f + expf(-v.y));
            v.z = v.z / (1.f + expf(-v.z));
            v.w = v.w / (1.f + expf(-v.w));
        }
        if (EPI == 3) {
            float4 r = *(const float4*)(resid + (size_t)row * ldr + col);
            v.x += r.x; v.y += r.y; v.z += r.z; v.w += r.w;
        }
        *(float4*)(C + (size_t)row * ldc + col) = v;
    }
}

// LayerNorm over 256, in-place on g_ef. One warp per edge.
__global__ void k_ln(const float* __restrict__ gam, const float* __restrict__ bet) {
    int wid = blockIdx.x * (blockDim.x >> 5) + (threadIdx.x >> 5);
    int lane = threadIdx.x & 31;
    if (wid >= BE) return;
    float* row = g_ef + (size_t)wid * Hh;
    float4 x0 = ((float4*)row)[lane];
    float4 x1 = ((float4*)row)[lane + 32];
    float s  = x0.x + x0.y + x0.z + x0.w + x1.x + x1.y + x1.z + x1.w;
    float ss = x0.x*x0.x + x0.y*x0.y + x0.z*x0.z + x0.w*x0.w
             + x1.x*x1.x + x1.y*x1.y + x1.z*x1.z + x1.w*x1.w;
#pragma unroll
    for (int o = 16; o; o >>= 1) {
        s  += __shfl_xor_sync(0xffffffffu, s,  o);
        ss += __shfl_xor_sync(0xffffffffu, ss, o);
    }
    float mu  = s * (1.f / 256.f);
    float var = ss * (1.f / 256.f) - mu * mu;
    float rstd = rsqrtf(var + 1e-5f);
    float4 g0 = ((const float4*)gam)[lane], g1 = ((const float4*)gam)[lane + 32];
    float4 b0 = ((const float4*)bet)[lane], b1 = ((const float4*)bet)[lane + 32];
    x0.x = (x0.x - mu) * rstd * g0.x + b0.x;
    x0.y = (x0.y - mu) * rstd * g0.y + b0.y;
    x0.z = (x0.z - mu) * rstd * g0.z + b0.z;
    x0.w = (x0.w - mu) * rstd * g0.w + b0.w;
    x1.x = (x1.x - mu) * rstd * g1.x + b1.x;
    x1.y = (x1.y - mu) * rstd * g1.y + b1.y;
    x1.z = (x1.z - mu) * rstd * g1.z + b1.z;
    x1.w = (x1.w - mu) * rstd * g1.w + b1.w;
    ((float4*)row)[lane]      = x0;
    ((float4*)row)[lane + 32] = x1;
}

// per-edge scalar: w = (silu hidden in g_mid) . coord_w2. One warp per edge.
__global__ void k_wdot(const float* __restrict__ cw2) {
    int wid = blockIdx.x * (blockDim.x >> 5) + (threadIdx.x >> 5);
    int lane = threadIdx.x & 31;
    if (wid >= BE) return;
    const float* row = g_mid + (size_t)wid * Hh;
    float4 a0 = ((const float4*)row)[lane];
    float4 a1 = ((const float4*)row)[lane + 32];
    float4 w0 = ((const float4*)cw2)[lane];
    float4 w1 = ((const float4*)cw2)[lane + 32];
    float s = a0.x*w0.x + a0.y*w0.y + a0.z*w0.z + a0.w*w0.w
            + a1.x*w1.x + a1.y*w1.y + a1.z*w1.z + a1.w*w1.w;
#pragma unroll
    for (int o = 16; o; o >>= 1) s += __shfl_xor_sync(0xffffffffu, s, o);
    if (lane == 0) g_wsc[wid] = s;
}

__global__ void k_init_coord(const float* __restrict__ coord, float* __restrict__ outc) {
    int idx = blockIdx.x * blockDim.x + threadIdx.x;
    if (idx < Bc * Nn * 3) outc[idx] = coord[idx];
}

__global__ void k_zero_agg() {
    int idx = blockIdx.x * blockDim.x + threadIdx.x;
    if (idx < BNr * Hh) g_agg[idx] = 0.f;
}

// Scatter edge contributions: coord update + edge_feat segment-sum. One warp/edge.
__global__ void k_scatter(const int* __restrict__ ei, float* __restrict__ outc) {
    int wid = blockIdx.x * (blockDim.x >> 5) + (threadIdx.x >> 5);
    int lane = threadIdx.x & 31;
    if (wid >= BE) return;
    int b = wid / Ee, j = wid - b * Ee;
    int i = ei[j];
    float wv = g_wsc[wid];
    if (lane < 3)
        atomicAdd(&outc[((size_t)b * Nn + i) * 3 + lane], g_cdiff[wid * 3 + lane] * wv);
    float* arow = g_agg + ((size_t)b * Nn + i) * Hh;
    const float* ef = g_ef + (size_t)wid * Hh;
#pragma unroll
    for (int t = 0; t < 8; t++) {
        int c = t * 32 + lane;
        atomicAdd(&arow[c], ef[c]);
    }
}

// build node MLP input [h (128) | agg (256)]. One warp per node row.
__global__ void k_nodein(const float* __restrict__ h) {
    int wid = blockIdx.x * (blockDim.x >> 5) + (threadIdx.x >> 5);
    int lane = threadIdx.x & 31;
    if (wid >= BNr) return;
    float* dst = g_nodein + (size_t)wid * (Hh + Ff);
    ((float4*)dst)[lane] = ((const float4*)(h + (size_t)wid * Ff))[lane];
    const float4* a4 = (const float4*)(g_agg + (size_t)wid * Hh);
    ((float4*)dst)[32 + lane] = a4[lane];
    ((float4*)dst)[64 + lane] = a4[32 + lane];
}

// ---------------- launch ----------------
extern "C" void kernel_launch(void* const* d_in, const int* in_sizes, int n_in,
                              void* d_out, int out_size) {
    const float* h     = (const float*)d_in[0];
    const float* coord = (const float*)d_in[1];
    const int*   ei    = (const int*)d_in[2];
    const float* ew1   = (const float*)d_in[3];
    const float* eb1   = (const float*)d_in[4];
    const float* ew2   = (const float*)d_in[5];
    const float* eb2   = (const float*)d_in[6];
    const float* lng   = (const float*)d_in[7];
    const float* lnb   = (const float*)d_in[8];
    const float* nw1   = (const float*)d_in[9];
    const float* nb1   = (const float*)d_in[10];
    const float* nw2   = (const float*)d_in[11];
    const float* nb2   = (const float*)d_in[12];
    const float* cw1   = (const float*)d_in[13];
    const float* cb1   = (const float*)d_in[14];
    const float* cw2   = (const float*)d_in[15];

    float* out_h = (float*)d_out;
    float* out_c = out_h + (size_t)BNr * Ff;

    void *p_feat, *p_mid, *p_ef, *p_w1cat, *p_nodein, *p_nodemid;
    cudaGetSymbolAddress(&p_feat,    g_feat);
    cudaGetSymbolAddress(&p_mid,     g_mid);
    cudaGetSymbolAddress(&p_ef,      g_ef);
    cudaGetSymbolAddress(&p_w1cat,   g_w1cat);
    cudaGetSymbolAddress(&p_nodein,  g_nodein);
    cudaGetSymbolAddress(&p_nodemid, g_nodemid);
    const float* featp   = (const float*)p_feat;
    float*       midp    = (float*)p_mid;
    float*       efp     = (float*)p_ef;
    const float* w1catp  = (const float*)p_w1cat;
    const float* nodeinp = (const float*)p_nodein;
    float*       nodemidp= (float*)p_nodemid;

    // weight transform + edge feature build (independent of later stages)
    k_w1cat<<<(FEATN * Hh + 255) / 256, 256>>>(ew1);
    k_edge<<<BE / 8, 256>>>(h, coord, ei);
    // init output coords + zero agg early (before scatter)
    k_init_coord<<<(Bc * Nn * 3 + 255) / 256, 256>>>(coord, out_c);
    k_zero_agg<<<(BNr * Hh + 255) / 256, 256>>>();

    // GEMM1: hmid = silu(feat @ W1cat + b1)   (262144 x 268) @ (268 x 256)
    k_gemm<2><<<dim3(Hh / 64, BE / 64), 256>>>(featp, w1catp, midp,
        BE, Hh, FEATN, FEATN, Hh, Hh, eb1, nullptr, 0);

    // GEMM2 per head: combined[:, h*64:(h+1)*64] = hmid_h @ w2[h] + b2[h]
    for (int hd = 0; hd < NHh; hd++) {
        k_gemm<1><<<dim3(1, BE / 64), 256>>>(
            midp + hd * Dd, ew2 + (size_t)hd * Dd * Dd, efp + hd * Dd,
            BE, Dd, Dd, Hh, Dd, Hh, eb2 + hd * Dd, nullptr, 0);
    }

    // LayerNorm in-place
    k_ln<<<BE / 8, 256>>>(lng, lnb);

    // GEMM3: T = silu(edge_feat @ coord_w1 + cb1)  -> reuse g_mid
    k_gemm<2><<<dim3(Hh / 64, BE / 64), 256>>>(efp, cw1, midp,
        BE, Hh, Hh, Hh, Hh, Hh, cb1, nullptr, 0);

    // per-edge scalar w = T . coord_w2
    k_wdot<<<BE / 8, 256>>>(cw2);

    // scatter: coord atomics + agg atomics
    k_scatter<<<BE / 8, 256>>>(ei, out_c);

    // node MLP
    k_nodein<<<BNr / 8, 256>>>(h);
    k_gemm<2><<<dim3(Hh / 64, BNr / 64), 256>>>(nodeinp, nw1, nodemidp,
        BNr, Hh, Hh + Ff, Hh + Ff, Hh, Hh, nb1, nullptr, 0);
    k_gemm<3><<<dim3(Ff / 64, BNr / 64), 256>>>(nodemidp, nw2, out_h,
        BNr, Ff, Hh, Hh, Ff, Ff, nb2, h, Ff);
}

// round 5
// speedup vs baseline: 1.8225x; 1.8225x over previous
#include <cuda_runtime.h>
#include <math.h>
#include <stdint.h>

// Problem constants (fixed shapes)
#define Bc   2
#define Nn   8192
#define Ff   128
#define Ee   131072
#define Hh   256
#define NHh  4
#define Dd   64
#define FEATN 268
#define FEATP 288          // padded to multiple of 32 for GEMM BK
#define BE   (Bc*Ee)       // 262144 edge rows
#define BNr  (Bc*Nn)       // 16384 node rows

// ---------------- static scratch ----------------
static __device__ float g_feat[(size_t)BE * FEATP];
static __device__ float g_mid[(size_t)BE * Hh];
static __device__ float g_ef[(size_t)BE * Hh];
static __device__ float g_cdiff[BE * 3];
static __device__ float g_wsc[BE];
static __device__ float g_agg[BNr * Hh];
static __device__ float g_nodein[BNr * (Hh + Ff)];
static __device__ float g_nodemid[BNr * Hh];
static __device__ float g_w1cat[FEATP * Hh];   // (288, 256), rows >=268 zero
static __device__ float g_w2cat[Hh * Hh];      // block-diagonal 256x256

// ---------------- helpers ----------------
__device__ __forceinline__ uint32_t f2tf(float x) {
    uint32_t r; asm("cvt.rna.tf32.f32 %0, %1;" : "=r"(r) : "f"(x)); return r;
}
__device__ __forceinline__ void ldsm4(uint32_t& r0, uint32_t& r1, uint32_t& r2, uint32_t& r3, uint32_t a) {
    asm volatile("ldmatrix.sync.aligned.m8n8.x4.shared.b16 {%0,%1,%2,%3}, [%4];"
                 : "=r"(r0), "=r"(r1), "=r"(r2), "=r"(r3) : "r"(a));
}
__device__ __forceinline__ void mma8(float* c, const uint32_t* a, const uint32_t* b) {
    asm volatile("mma.sync.aligned.m16n8k8.row.col.f32.tf32.tf32.f32 "
                 "{%0,%1,%2,%3}, {%4,%5,%6,%7}, {%8,%9}, {%0,%1,%2,%3};"
                 : "+f"(c[0]), "+f"(c[1]), "+f"(c[2]), "+f"(c[3])
                 : "r"(a[0]), "r"(a[1]), "r"(a[2]), "r"(a[3]), "r"(b[0]), "r"(b[1]));
}
__device__ __forceinline__ float silu_f(float x) { return x / (1.f + expf(-x)); }

// ---------------- small kernels ----------------
__global__ void k_w1cat(const float* __restrict__ w1) {
    int idx = blockIdx.x * blockDim.x + threadIdx.x;
    if (idx >= FEATP * Hh) return;
    int f = idx >> 8, c = idx & 255;
    g_w1cat[idx] = (f < FEATN) ? w1[(((c >> 6) * FEATN) + f) * Dd + (c & 63)] : 0.f;
}

__global__ void k_w2cat(const float* __restrict__ w2) {
    int idx = blockIdx.x * blockDim.x + threadIdx.x;
    if (idx >= Hh * Hh) return;
    int k = idx >> 8, n = idx & 255;
    float v = 0.f;
    if ((k >> 6) == (n >> 6))
        v = w2[(k >> 6) * (Dd * Dd) + (k & 63) * Dd + (n & 63)];
    g_w2cat[idx] = v;
}

// One warp per edge: gather h rows, geometry features, zero-pad
__global__ void k_edge(const float* __restrict__ h, const float* __restrict__ coord,
                       const int* __restrict__ ei) {
    int wid = blockIdx.x * (blockDim.x >> 5) + (threadIdx.x >> 5);
    int lane = threadIdx.x & 31;
    if (wid >= BE) return;
    int b = wid / Ee, j = wid - b * Ee;
    int i = ei[j], k = ei[Ee + j];
    float* feat = g_feat + (size_t)wid * FEATP;
    const float4* hi4 = (const float4*)(h + ((size_t)b * Nn + i) * Ff);
    const float4* hk4 = (const float4*)(h + ((size_t)b * Nn + k) * Ff);
    ((float4*)feat)[lane]      = hi4[lane];
    ((float4*)feat)[32 + lane] = hk4[lane];
    if (lane < 20) feat[FEATN + lane] = 0.f;
    if (lane == 0) {
        const float* ci = coord + ((size_t)b * Nn + i) * 3;
        const float* ck = coord + ((size_t)b * Nn + k) * 3;
        float cix = ci[0], ciy = ci[1], ciz = ci[2];
        float ckx = ck[0], cky = ck[1], ckz = ck[2];
        float dx = cix - ckx, dy = ciy - cky, dz = ciz - ckz;
        float radial = dx * dx + dy * dy + dz * dz;
        float dist = sqrtf(radial);
        float dotv = cix * ckx + ciy * cky + ciz * ckz;
        float inva = 1.f / (dist + 1e-8f);
        float ax = dx * inva, ay = dy * inva, az = dz * inva;
        float crx = ciy * ckz - ciz * cky;
        float cry = ciz * ckx - cix * ckz;
        float crz = cix * cky - ciy * ckx;
        float nb = sqrtf(crx * crx + cry * cry + crz * crz);
        float invb = 1.f / (nb + 1e-8f);
        float bx = crx * invb, by = cry * invb, bz = crz * invb;
        float cx = ay * bz - az * by;
        float cy = az * bx - ax * bz;
        float cz = ax * by - ay * bx;
        float na  = sqrtf(ax * ax + ay * ay + az * az);
        float nbv = sqrtf(bx * bx + by * by + bz * bz);
        float ncv = sqrtf(cx * cx + cy * cy + cz * cz);
        bool bad = (na < 1e-6f) || (nbv < 1e-6f) || (ncv < 1e-6f);
        if (bad) { ax = 1.f; bx = 0.f; cx = 0.f;
                   ay = 0.f; by = 1.f; cy = 0.f;
                   az = 0.f; bz = 0.f; cz = 1.f; }
        feat[256] = radial; feat[257] = dist; feat[258] = dotv;
        feat[259] = ax; feat[260] = bx; feat[261] = cx;
        feat[262] = ay; feat[263] = by; feat[264] = cy;
        feat[265] = az; feat[266] = bz; feat[267] = cz;
        g_cdiff[wid * 3 + 0] = dx;
        g_cdiff[wid * 3 + 1] = dy;
        g_cdiff[wid * 3 + 2] = dz;
    }
}

// ---------------- tf32 tensor-core GEMM ----------------
// Block tile 128x128, BK=32, 8 warps (2x4), warp tile 64x32, m16n8k8 tf32 MMA.
// EPI: 2 bias+silu store, 3 bias+residual store, 4 bias+silu+dot(extra)->atomic wsc (no store), 5 bias store
#define AST 36
#define BST 36

template <int EPI>
__global__ void __launch_bounds__(256) k_gemm_t(
    const float* __restrict__ A, const float* __restrict__ B, float* __restrict__ C,
    int K, int lda, int ldb, int ldc,
    const float* __restrict__ bias, const float* __restrict__ extra, int ldr,
    float* __restrict__ wsc)
{
    __shared__ __align__(16) uint32_t As[128 * AST];
    __shared__ __align__(16) uint32_t Bs[128 * BST];
    const int tid = threadIdx.x, lane = tid & 31, wid = tid >> 5;
    const int wm = wid >> 2, wn = wid & 3;
    const int m0 = blockIdx.y * 128, n0 = blockIdx.x * 128;

    // A tile load map: rows am+32i, float4 at col ak
    const int am = tid >> 3;
    const int ak = (tid & 7) << 2;
    // B tile load map: row bk+8i, float4 at col bn (transposed into smem)
    const int bk = tid & 7;
    const int bn = ((tid >> 3) & 3) * 4 + (tid >> 5) * 16;

    const float* Ag = A + (size_t)m0 * lda;
    const float* Bg = B + n0;

    float acc[4][4][4];
#pragma unroll
    for (int i = 0; i < 4; i++)
#pragma unroll
        for (int j = 0; j < 4; j++) { acc[i][j][0] = 0.f; acc[i][j][1] = 0.f; acc[i][j][2] = 0.f; acc[i][j][3] = 0.f; }

    float4 pa[4], pb[4];
#pragma unroll
    for (int i = 0; i < 4; i++) {
        pa[i] = *(const float4*)(Ag + (size_t)(am + 32 * i) * lda + ak);
        pb[i] = *(const float4*)(Bg + (size_t)(bk + 8 * i) * ldb + bn);
    }

    const uint32_t as_base = (uint32_t)__cvta_generic_to_shared(As);
    const uint32_t bs_base = (uint32_t)__cvta_generic_to_shared(Bs);
    const int a_r = wm * 64 + (lane & 15);
    const int a_q = (lane >> 4) << 2;
    const int b_r = wn * 32 + (lane & 7) + ((lane >> 4) << 3);
    const int b_q = ((lane >> 3) & 1) << 2;

    for (int k0 = 0; k0 < K; k0 += 32) {
#pragma unroll
        for (int i = 0; i < 4; i++) {
            uint4 v = make_uint4(f2tf(pa[i].x), f2tf(pa[i].y), f2tf(pa[i].z), f2tf(pa[i].w));
            *(uint4*)&As[(am + 32 * i) * AST + ak] = v;
            int kk = bk + 8 * i;
            Bs[(bn + 0) * BST + kk] = f2tf(pb[i].x);
            Bs[(bn + 1) * BST + kk] = f2tf(pb[i].y);
            Bs[(bn + 2) * BST + kk] = f2tf(pb[i].z);
            Bs[(bn + 3) * BST + kk] = f2tf(pb[i].w);
        }
        __syncthreads();
        if (k0 + 32 < K) {
#pragma unroll
            for (int i = 0; i < 4; i++) {
                pa[i] = *(const float4*)(Ag + (size_t)(am + 32 * i) * lda + (k0 + 32) + ak);
                pb[i] = *(const float4*)(Bg + (size_t)(k0 + 32 + bk + 8 * i) * ldb + bn);
            }
        }
#pragma unroll
        for (int kk = 0; kk < 4; kk++) {
            uint32_t af[4][4], bf[4][2];
#pragma unroll
            for (int mi = 0; mi < 4; mi++)
                ldsm4(af[mi][0], af[mi][1], af[mi][2], af[mi][3],
                      as_base + (((a_r + mi * 16) * AST + kk * 8 + a_q) << 2));
#pragma unroll
            for (int np = 0; np < 2; np++) {
                uint32_t r0, r1, r2, r3;
                ldsm4(r0, r1, r2, r3,
                      bs_base + (((b_r + np * 16) * BST + kk * 8 + b_q) << 2));
                bf[np * 2][0] = r0; bf[np * 2][1] = r1;
                bf[np * 2 + 1][0] = r2; bf[np * 2 + 1][1] = r3;
            }
#pragma unroll
            for (int mi = 0; mi < 4; mi++)
#pragma unroll
                for (int ni = 0; ni < 4; ni++)
                    mma8(acc[mi][ni], af[mi], bf[ni]);
        }
        __syncthreads();
    }

    // ---------------- epilogue ----------------
    const int row0 = m0 + wm * 64 + (lane >> 2);
    const int colw = wn * 32 + ((lane & 3) << 1);
#pragma unroll
    for (int mi = 0; mi < 4; mi++) {
        float slo = 0.f, shi = 0.f;
        int r = row0 + mi * 16;
#pragma unroll
        for (int ni = 0; ni < 4; ni++) {
            int col = n0 + colw + ni * 8;
            float2 bb = *(const float2*)(bias + col);
            float v0 = acc[mi][ni][0] + bb.x, v1 = acc[mi][ni][1] + bb.y;
            float v2 = acc[mi][ni][2] + bb.x, v3 = acc[mi][ni][3] + bb.y;
            if (EPI == 2 || EPI == 4) {
                v0 = silu_f(v0); v1 = silu_f(v1); v2 = silu_f(v2); v3 = silu_f(v3);
            }
            if (EPI == 3) {
                float2 ra = *(const float2*)(extra + (size_t)r * ldr + col);
                float2 rb = *(const float2*)(extra + (size_t)(r + 8) * ldr + col);
                v0 += ra.x; v1 += ra.y; v2 += rb.x; v3 += rb.y;
            }
            if (EPI == 4) {
                float2 w = *(const float2*)(extra + col);
                slo += v0 * w.x + v1 * w.y;
                shi += v2 * w.x + v3 * w.y;
            } else {
                *(float2*)(C + (size_t)r * ldc + col)       = make_float2(v0, v1);
                *(float2*)(C + (size_t)(r + 8) * ldc + col) = make_float2(v2, v3);
            }
        }
        if (EPI == 4) {
            slo += __shfl_xor_sync(0xffffffffu, slo, 1);
            slo += __shfl_xor_sync(0xffffffffu, slo, 2);
            shi += __shfl_xor_sync(0xffffffffu, shi, 1);
            shi += __shfl_xor_sync(0xffffffffu, shi, 2);
            if ((lane & 3) == 0) {
                atomicAdd(wsc + r, slo);
                atomicAdd(wsc + r + 8, shi);
            }
        }
    }
}

// LayerNorm over 256, in-place on g_ef
__global__ void k_ln(const float* __restrict__ gam, const float* __restrict__ bet) {
    int wid = blockIdx.x * (blockDim.x >> 5) + (threadIdx.x >> 5);
    int lane = threadIdx.x & 31;
    if (wid >= BE) return;
    float* row = g_ef + (size_t)wid * Hh;
    float4 x0 = ((float4*)row)[lane];
    float4 x1 = ((float4*)row)[lane + 32];
    float s  = x0.x + x0.y + x0.z + x0.w + x1.x + x1.y + x1.z + x1.w;
    float ss = x0.x*x0.x + x0.y*x0.y + x0.z*x0.z + x0.w*x0.w
             + x1.x*x1.x + x1.y*x1.y + x1.z*x1.z + x1.w*x1.w;
#pragma unroll
    for (int o = 16; o; o >>= 1) {
        s  += __shfl_xor_sync(0xffffffffu, s,  o);
        ss += __shfl_xor_sync(0xffffffffu, ss, o);
    }
    float mu  = s * (1.f / 256.f);
    float var = ss * (1.f / 256.f) - mu * mu;
    float rstd = rsqrtf(var + 1e-5f);
    float4 g0 = ((const float4*)gam)[lane], g1 = ((const float4*)gam)[lane + 32];
    float4 b0 = ((const float4*)bet)[lane], b1 = ((const float4*)bet)[lane + 32];
    x0.x = (x0.x - mu) * rstd * g0.x + b0.x;
    x0.y = (x0.y - mu) * rstd * g0.y + b0.y;
    x0.z = (x0.z - mu) * rstd * g0.z + b0.z;
    x0.w = (x0.w - mu) * rstd * g0.w + b0.w;
    x1.x = (x1.x - mu) * rstd * g1.x + b1.x;
    x1.y = (x1.y - mu) * rstd * g1.y + b1.y;
    x1.z = (x1.z - mu) * rstd * g1.z + b1.z;
    x1.w = (x1.w - mu) * rstd * g1.w + b1.w;
    ((float4*)row)[lane]      = x0;
    ((float4*)row)[lane + 32] = x1;
}

__global__ void k_init_coord(const float* __restrict__ coord, float* __restrict__ outc) {
    int idx = blockIdx.x * blockDim.x + threadIdx.x;
    if (idx < Bc * Nn * 3) outc[idx] = coord[idx];
}

__global__ void k_zero() {
    int idx = blockIdx.x * blockDim.x + threadIdx.x;
    if (idx < BNr * Hh) g_agg[idx] = 0.f;
    if (idx < BE) g_wsc[idx] = 0.f;
}

// Scatter: coord atomics + edge_feat segment-sum
__global__ void k_scatter(const int* __restrict__ ei, float* __restrict__ outc) {
    int wid = blockIdx.x * (blockDim.x >> 5) + (threadIdx.x >> 5);
    int lane = threadIdx.x & 31;
    if (wid >= BE) return;
    int b = wid / Ee, j = wid - b * Ee;
    int i = ei[j];
    float wv = g_wsc[wid];
    if (lane < 3)
        atomicAdd(&outc[((size_t)b * Nn + i) * 3 + lane], g_cdiff[wid * 3 + lane] * wv);
    float* arow = g_agg + ((size_t)b * Nn + i) * Hh;
    const float* ef = g_ef + (size_t)wid * Hh;
#pragma unroll
    for (int t = 0; t < 8; t++) {
        int c = t * 32 + lane;
        atomicAdd(&arow[c], ef[c]);
    }
}

__global__ void k_nodein(const float* __restrict__ h) {
    int wid = blockIdx.x * (blockDim.x >> 5) + (threadIdx.x >> 5);
    int lane = threadIdx.x & 31;
    if (wid >= BNr) return;
    float* dst = g_nodein + (size_t)wid * (Hh + Ff);
    ((float4*)dst)[lane] = ((const float4*)(h + (size_t)wid * Ff))[lane];
    const float4* a4 = (const float4*)(g_agg + (size_t)wid * Hh);
    ((float4*)dst)[32 + lane] = a4[lane];
    ((float4*)dst)[64 + lane] = a4[32 + lane];
}

// ---------------- launch ----------------
extern "C" void kernel_launch(void* const* d_in, const int* in_sizes, int n_in,
                              void* d_out, int out_size) {
    const float* h     = (const float*)d_in[0];
    const float* coord = (const float*)d_in[1];
    const int*   ei    = (const int*)d_in[2];
    const float* ew1   = (const float*)d_in[3];
    const float* eb1   = (const float*)d_in[4];
    const float* ew2   = (const float*)d_in[5];
    const float* eb2   = (const float*)d_in[6];
    const float* lng   = (const float*)d_in[7];
    const float* lnb   = (const float*)d_in[8];
    const float* nw1   = (const float*)d_in[9];
    const float* nb1   = (const float*)d_in[10];
    const float* nw2   = (const float*)d_in[11];
    const float* nb2   = (const float*)d_in[12];
    const float* cw1   = (const float*)d_in[13];
    const float* cb1   = (const float*)d_in[14];
    const float* cw2   = (const float*)d_in[15];

    float* out_h = (float*)d_out;
    float* out_c = out_h + (size_t)BNr * Ff;

    void *p_feat, *p_mid, *p_ef, *p_w1cat, *p_w2cat, *p_nodein, *p_nodemid, *p_wsc;
    cudaGetSymbolAddress(&p_feat,    g_feat);
    cudaGetSymbolAddress(&p_mid,     g_mid);
    cudaGetSymbolAddress(&p_ef,      g_ef);
    cudaGetSymbolAddress(&p_w1cat,   g_w1cat);
    cudaGetSymbolAddress(&p_w2cat,   g_w2cat);
    cudaGetSymbolAddress(&p_nodein,  g_nodein);
    cudaGetSymbolAddress(&p_nodemid, g_nodemid);
    cudaGetSymbolAddress(&p_wsc,     g_wsc);
    const float* featp    = (const float*)p_feat;
    float*       midp     = (float*)p_mid;
    float*       efp      = (float*)p_ef;
    const float* w1catp   = (const float*)p_w1cat;
    const float* w2catp   = (const float*)p_w2cat;
    const float* nodeinp  = (const float*)p_nodein;
    float*       nodemidp = (float*)p_nodemid;
    float*       wscp     = (float*)p_wsc;

    k_w1cat<<<(FEATP * Hh + 255) / 256, 256>>>(ew1);
    k_w2cat<<<(Hh * Hh + 255) / 256, 256>>>(ew2);
    k_edge<<<BE / 8, 256>>>(h, coord, ei);
    k_init_coord<<<(Bc * Nn * 3 + 255) / 256, 256>>>(coord, out_c);
    k_zero<<<(BNr * Hh + 255) / 256, 256>>>();

    // GEMM1: g_mid = silu(feat @ W1cat + b1)   (262144 x 288) @ (288 x 256)
    k_gemm_t<2><<<dim3(Hh / 128, BE / 128), 256>>>(featp, w1catp, midp,
        FEATP, FEATP, Hh, Hh, eb1, nullptr, 0, nullptr);

    // GEMM2 (block-diag): g_ef = g_mid @ W2cat + b2
    k_gemm_t<5><<<dim3(Hh / 128, BE / 128), 256>>>(midp, w2catp, efp,
        Hh, Hh, Hh, Hh, eb2, nullptr, 0, nullptr);

    // LayerNorm in place
    k_ln<<<BE / 8, 256>>>(lng, lnb);

    // GEMM3 fused: w = silu(ef @ cw1 + cb1) . cw2 -> atomic into g_wsc (no C)
    k_gemm_t<4><<<dim3(Hh / 128, BE / 128), 256>>>(efp, cw1, nullptr,
        Hh, Hh, Hh, 0, cb1, cw2, 0, wscp);

    // scatter: coord atomics + agg atomics
    k_scatter<<<BE / 8, 256>>>(ei, out_c);

    // node MLP
    k_nodein<<<BNr / 8, 256>>>(h);
    k_gemm_t<2><<<dim3(Hh / 128, BNr / 128), 256>>>(nodeinp, nw1, nodemidp,
        Hh + Ff, Hh + Ff, Hh, Hh, nb1, nullptr, 0, nullptr);
    k_gemm_t<3><<<dim3(Ff / 128, BNr / 128), 256>>>(nodemidp, nw2, out_h,
        Hh, Hh, Ff, Ff, nb2, h, Ff, nullptr);
}

// round 6
// speedup vs baseline: 2.0931x; 1.1484x over previous
#include <cuda_runtime.h>
#include <math.h>
#include <stdint.h>

// Problem constants (fixed shapes)
#define Bc   2
#define Nn   8192
#define Ff   128
#define Ee   131072
#define Hh   256
#define NHh  4
#define Dd   64
#define FEATN 268
#define FEATP 288          // padded K for GEMM1
#define BE   (Bc*Ee)       // 262144 edge rows
#define BNr  (Bc*Nn)       // 16384 node rows

// ---------------- static scratch ----------------
static __device__ float g_mid[(size_t)BE * Hh];
static __device__ float g_ef[(size_t)BE * Hh];
static __device__ float g_geo[(size_t)BE * 32];   // 12 geometry feats + 20 zeros
static __device__ float g_cdiff[BE * 3];
static __device__ float g_wsc[BE];
static __device__ float g_agg[BNr * Hh];
static __device__ float g_nodemid[BNr * Hh];
static __device__ float g_w1cat[FEATP * Hh];      // (288, 256), rows >=268 zero
static __device__ float g_w2cat2[2 * 128 * 128];  // two 2-head block-diag tiles

// ---------------- helpers ----------------
__device__ __forceinline__ uint32_t f2tf(float x) {
    uint32_t r; asm("cvt.rna.tf32.f32 %0, %1;" : "=r"(r) : "f"(x)); return r;
}
__device__ __forceinline__ void ldsm4(uint32_t& r0, uint32_t& r1, uint32_t& r2, uint32_t& r3, uint32_t a) {
    asm volatile("ldmatrix.sync.aligned.m8n8.x4.shared.b16 {%0,%1,%2,%3}, [%4];"
                 : "=r"(r0), "=r"(r1), "=r"(r2), "=r"(r3) : "r"(a));
}
__device__ __forceinline__ void mma8(float* c, const uint32_t* a, const uint32_t* b) {
    asm volatile("mma.sync.aligned.m16n8k8.row.col.f32.tf32.tf32.f32 "
                 "{%0,%1,%2,%3}, {%4,%5,%6,%7}, {%8,%9}, {%0,%1,%2,%3};"
                 : "+f"(c[0]), "+f"(c[1]), "+f"(c[2]), "+f"(c[3])
                 : "r"(a[0]), "r"(a[1]), "r"(a[2]), "r"(a[3]), "r"(b[0]), "r"(b[1]));
}
__device__ __forceinline__ float silu_f(float x) { return x / (1.f + expf(-x)); }
__device__ __forceinline__ void red4(float* addr, float4 v) {
    asm volatile("red.global.add.v4.f32 [%0], {%1,%2,%3,%4};"
                 :: "l"(addr), "f"(v.x), "f"(v.y), "f"(v.z), "f"(v.w) : "memory");
}

// ---------------- combined init: zero agg/wsc, copy coord, build weights ----------------
__global__ void k_misc(const float* __restrict__ coord, float* __restrict__ outc,
                       const float* __restrict__ w1, const float* __restrict__ w2) {
    int idx = blockIdx.x * blockDim.x + threadIdx.x;
    if (idx < BNr * Hh) g_agg[idx] = 0.f;
    if (idx < BE) g_wsc[idx] = 0.f;
    if (idx < Bc * Nn * 3) outc[idx] = coord[idx];
    if (idx < FEATP * Hh) {
        int f = idx >> 8, c = idx & 255;
        g_w1cat[idx] = (f < FEATN) ? w1[(((c >> 6) * FEATN) + f) * Dd + (c & 63)] : 0.f;
    }
    if (idx < 2 * 128 * 128) {
        int p = idx >> 14, kk = (idx >> 7) & 127, n = idx & 127;
        g_w2cat2[idx] = ((kk >> 6) == (n >> 6))
            ? w2[((p << 1) + (kk >> 6)) * (Dd * Dd) + (kk & 63) * Dd + (n & 63)] : 0.f;
    }
}

// geometry features per edge (thread per edge)
__global__ void k_geo(const float* __restrict__ coord, const int* __restrict__ ei) {
    int e = blockIdx.x * blockDim.x + threadIdx.x;
    if (e >= BE) return;
    int b = (e >= Ee) ? 1 : 0, j = e - b * Ee;
    int i = ei[j], k = ei[Ee + j];
    const float* ci = coord + ((size_t)b * Nn + i) * 3;
    const float* ck = coord + ((size_t)b * Nn + k) * 3;
    float cix = ci[0], ciy = ci[1], ciz = ci[2];
    float ckx = ck[0], cky = ck[1], ckz = ck[2];
    float dx = cix - ckx, dy = ciy - cky, dz = ciz - ckz;
    float radial = dx * dx + dy * dy + dz * dz;
    float dist = sqrtf(radial);
    float dotv = cix * ckx + ciy * cky + ciz * ckz;
    float inva = 1.f / (dist + 1e-8f);
    float ax = dx * inva, ay = dy * inva, az = dz * inva;
    float crx = ciy * ckz - ciz * cky;
    float cry = ciz * ckx - cix * ckz;
    float crz = cix * cky - ciy * ckx;
    float nb = sqrtf(crx * crx + cry * cry + crz * crz);
    float invb = 1.f / (nb + 1e-8f);
    float bx = crx * invb, by = cry * invb, bz = crz * invb;
    float cx = ay * bz - az * by;
    float cy = az * bx - ax * bz;
    float cz = ax * by - ay * bx;
    float na  = sqrtf(ax * ax + ay * ay + az * az);
    float nbv = sqrtf(bx * bx + by * by + bz * bz);
    float ncv = sqrtf(cx * cx + cy * cy + cz * cz);
    bool bad = (na < 1e-6f) || (nbv < 1e-6f) || (ncv < 1e-6f);
    if (bad) { ax = 1.f; bx = 0.f; cx = 0.f;
               ay = 0.f; by = 1.f; cy = 0.f;
               az = 0.f; bz = 0.f; cz = 1.f; }
    float4* g = (float4*)(g_geo + (size_t)e * 32);
    g[0] = make_float4(radial, dist, dotv, ax);
    g[1] = make_float4(bx, cx, ay, by);
    g[2] = make_float4(cy, az, bz, cz);
    float4 z = make_float4(0.f, 0.f, 0.f, 0.f);
    g[3] = z; g[4] = z; g[5] = z; g[6] = z; g[7] = z;
    g_cdiff[e * 3 + 0] = dx;
    g_cdiff[e * 3 + 1] = dy;
    g_cdiff[e * 3 + 2] = dz;
}

// ---------------- tf32 tensor-core GEMM ----------------
// Block tile 128x128, BK=32, 8 warps (2x4), warp tile 64x32, m16n8k8 tf32 MMA.
// EPI: 2 bias+silu store, 3 bias+residual store, 4 bias+silu+dot(extra)->atomic wsc, 5 bias store
// MODE: 0 normal A, 1 edge-gather A (h[i]|h[k]|geo), 2 node-split A (h|agg)
// NDIAG: A col-offset by n0, B is per-blockIdx.x 128x128 tile (block-diag pair GEMM)
#define AST 36
#define BST 36

template <int EPI, int MODE, bool NDIAG>
__global__ void __launch_bounds__(256) k_gemm_t(
    const float* __restrict__ A, const float* __restrict__ A2,
    const float* __restrict__ B, float* __restrict__ C,
    int K, int lda, int ldb, int ldc,
    const float* __restrict__ bias, const float* __restrict__ extra, int ldr,
    float* __restrict__ wsc, const int* __restrict__ ei, const float* __restrict__ geo)
{
    __shared__ __align__(16) uint32_t As[128 * AST];
    __shared__ __align__(16) uint32_t Bs[128 * BST];
    const int tid = threadIdx.x, lane = tid & 31, wid = tid >> 5;
    const int wm = wid >> 2, wn = wid & 3;
    const int m0 = blockIdx.y * 128, n0 = blockIdx.x * 128;

    const int am = tid >> 3;
    const int ak = (tid & 7) << 2;
    const int bk = tid & 7;
    const int bn = ((tid >> 3) & 3) * 4 + (tid >> 5) * 16;

    if (NDIAG) A += n0;
    const float* Bg = NDIAG ? (B + blockIdx.x * (128 * 128)) : (B + n0);

    // per-thread A row pointers
    const float* pA[4]; const float* pS[4]; const float* pG[4];
#pragma unroll
    for (int i = 0; i < 4; i++) {
        int r = m0 + am + 32 * i;
        if (MODE == 0) {
            pA[i] = A + (size_t)r * lda;
        } else if (MODE == 1) {
            int b = (m0 >= Ee) ? 1 : 0;
            int j = r - b * Ee;
            pA[i] = A + ((size_t)b * Nn + ei[j]) * Ff;
            pS[i] = A + ((size_t)b * Nn + ei[Ee + j]) * Ff;
            pG[i] = geo + (size_t)r * 32;
        } else {
            pA[i] = A + (size_t)r * 128;
            pS[i] = A2 + (size_t)r * 256;
        }
    }

    auto loadA = [&](int i, int kcol) -> float4 {
        if (MODE == 0) return *(const float4*)(pA[i] + kcol);
        if (MODE == 1) {
            if (kcol < 128) return *(const float4*)(pA[i] + kcol);
            if (kcol < 256) return *(const float4*)(pS[i] + (kcol - 128));
            return *(const float4*)(pG[i] + (kcol - 256));
        }
        if (kcol < 128) return *(const float4*)(pA[i] + kcol);
        return *(const float4*)(pS[i] + (kcol - 128));
    };

    float acc[4][4][4];
#pragma unroll
    for (int i = 0; i < 4; i++)
#pragma unroll
        for (int j = 0; j < 4; j++) { acc[i][j][0] = 0.f; acc[i][j][1] = 0.f; acc[i][j][2] = 0.f; acc[i][j][3] = 0.f; }

    float4 pa[4], pb[4];
#pragma unroll
    for (int i = 0; i < 4; i++) {
        pa[i] = loadA(i, ak);
        pb[i] = *(const float4*)(Bg + (size_t)(bk + 8 * i) * ldb + bn);
    }

    const uint32_t as_base = (uint32_t)__cvta_generic_to_shared(As);
    const uint32_t bs_base = (uint32_t)__cvta_generic_to_shared(Bs);
    const int a_r = wm * 64 + (lane & 15);
    const int a_q = (lane >> 4) << 2;
    const int b_r = wn * 32 + (lane & 7) + ((lane >> 4) << 3);
    const int b_q = ((lane >> 3) & 1) << 2;

    for (int k0 = 0; k0 < K; k0 += 32) {
#pragma unroll
        for (int i = 0; i < 4; i++) {
            uint4 v = make_uint4(f2tf(pa[i].x), f2tf(pa[i].y), f2tf(pa[i].z), f2tf(pa[i].w));
            *(uint4*)&As[(am + 32 * i) * AST + ak] = v;
            int kk = bk + 8 * i;
            Bs[(bn + 0) * BST + kk] = f2tf(pb[i].x);
            Bs[(bn + 1) * BST + kk] = f2tf(pb[i].y);
            Bs[(bn + 2) * BST + kk] = f2tf(pb[i].z);
            Bs[(bn + 3) * BST + kk] = f2tf(pb[i].w);
        }
        __syncthreads();
        if (k0 + 32 < K) {
#pragma unroll
            for (int i = 0; i < 4; i++) {
                pa[i] = loadA(i, k0 + 32 + ak);
                pb[i] = *(const float4*)(Bg + (size_t)(k0 + 32 + bk + 8 * i) * ldb + bn);
            }
        }
#pragma unroll
        for (int kk = 0; kk < 4; kk++) {
            uint32_t af[4][4], bf[4][2];
#pragma unroll
            for (int mi = 0; mi < 4; mi++)
                ldsm4(af[mi][0], af[mi][1], af[mi][2], af[mi][3],
                      as_base + (((a_r + mi * 16) * AST + kk * 8 + a_q) << 2));
#pragma unroll
            for (int np = 0; np < 2; np++) {
                uint32_t r0, r1, r2, r3;
                ldsm4(r0, r1, r2, r3,
                      bs_base + (((b_r + np * 16) * BST + kk * 8 + b_q) << 2));
                bf[np * 2][0] = r0; bf[np * 2][1] = r1;
                bf[np * 2 + 1][0] = r2; bf[np * 2 + 1][1] = r3;
            }
#pragma unroll
            for (int mi = 0; mi < 4; mi++)
#pragma unroll
                for (int ni = 0; ni < 4; ni++)
                    mma8(acc[mi][ni], af[mi], bf[ni]);
        }
        __syncthreads();
    }

    // ---------------- epilogue ----------------
    const int row0 = m0 + wm * 64 + (lane >> 2);
    const int colw = wn * 32 + ((lane & 3) << 1);
#pragma unroll
    for (int mi = 0; mi < 4; mi++) {
        float slo = 0.f, shi = 0.f;
        int r = row0 + mi * 16;
#pragma unroll
        for (int ni = 0; ni < 4; ni++) {
            int col = n0 + colw + ni * 8;
            float2 bb = *(const float2*)(bias + col);
            float v0 = acc[mi][ni][0] + bb.x, v1 = acc[mi][ni][1] + bb.y;
            float v2 = acc[mi][ni][2] + bb.x, v3 = acc[mi][ni][3] + bb.y;
            if (EPI == 2 || EPI == 4) {
                v0 = silu_f(v0); v1 = silu_f(v1); v2 = silu_f(v2); v3 = silu_f(v3);
            }
            if (EPI == 3) {
                float2 ra = *(const float2*)(extra + (size_t)r * ldr + col);
                float2 rb = *(const float2*)(extra + (size_t)(r + 8) * ldr + col);
                v0 += ra.x; v1 += ra.y; v2 += rb.x; v3 += rb.y;
            }
            if (EPI == 4) {
                float2 w = *(const float2*)(extra + col);
                slo += v0 * w.x + v1 * w.y;
                shi += v2 * w.x + v3 * w.y;
            } else {
                *(float2*)(C + (size_t)r * ldc + col)       = make_float2(v0, v1);
                *(float2*)(C + (size_t)(r + 8) * ldc + col) = make_float2(v2, v3);
            }
        }
        if (EPI == 4) {
            slo += __shfl_xor_sync(0xffffffffu, slo, 1);
            slo += __shfl_xor_sync(0xffffffffu, slo, 2);
            shi += __shfl_xor_sync(0xffffffffu, shi, 1);
            shi += __shfl_xor_sync(0xffffffffu, shi, 2);
            if ((lane & 3) == 0) {
                atomicAdd(wsc + r, slo);
                atomicAdd(wsc + r + 8, shi);
            }
        }
    }
}

// Fused LayerNorm (in-place on g_ef) + agg segment-sum (vector red). One warp per edge.
__global__ void k_lnscatter(const float* __restrict__ gam, const float* __restrict__ bet,
                            const int* __restrict__ ei) {
    int wid = blockIdx.x * (blockDim.x >> 5) + (threadIdx.x >> 5);
    int lane = threadIdx.x & 31;
    if (wid >= BE) return;
    float* row = g_ef + (size_t)wid * Hh;
    float4 x0 = ((float4*)row)[lane];
    float4 x1 = ((float4*)row)[lane + 32];
    float s  = x0.x + x0.y + x0.z + x0.w + x1.x + x1.y + x1.z + x1.w;
    float ss = x0.x*x0.x + x0.y*x0.y + x0.z*x0.z + x0.w*x0.w
             + x1.x*x1.x + x1.y*x1.y + x1.z*x1.z + x1.w*x1.w;
#pragma unroll
    for (int o = 16; o; o >>= 1) {
        s  += __shfl_xor_sync(0xffffffffu, s,  o);
        ss += __shfl_xor_sync(0xffffffffu, ss, o);
    }
    float mu  = s * (1.f / 256.f);
    float var = ss * (1.f / 256.f) - mu * mu;
    float rstd = rsqrtf(var + 1e-5f);
    float4 g0 = ((const float4*)gam)[lane], g1 = ((const float4*)gam)[lane + 32];
    float4 b0 = ((const float4*)bet)[lane], b1 = ((const float4*)bet)[lane + 32];
    x0.x = (x0.x - mu) * rstd * g0.x + b0.x;
    x0.y = (x0.y - mu) * rstd * g0.y + b0.y;
    x0.z = (x0.z - mu) * rstd * g0.z + b0.z;
    x0.w = (x0.w - mu) * rstd * g0.w + b0.w;
    x1.x = (x1.x - mu) * rstd * g1.x + b1.x;
    x1.y = (x1.y - mu) * rstd * g1.y + b1.y;
    x1.z = (x1.z - mu) * rstd * g1.z + b1.z;
    x1.w = (x1.w - mu) * rstd * g1.w + b1.w;
    ((float4*)row)[lane]      = x0;
    ((float4*)row)[lane + 32] = x1;
    int b = (wid >= Ee) ? 1 : 0, j = wid - b * Ee;
    int i = ei[j];
    float* arow = g_agg + ((size_t)b * Nn + i) * Hh;
    red4(arow + 4 * lane, x0);
    red4(arow + 128 + 4 * lane, x1);
}

// coord scatter: thread per edge
__global__ void k_coordscatter(const int* __restrict__ ei, float* __restrict__ outc) {
    int e = blockIdx.x * blockDim.x + threadIdx.x;
    if (e >= BE) return;
    int b = (e >= Ee) ? 1 : 0, j = e - b * Ee;
    int i = ei[j];
    float wv = g_wsc[e];
    float* dst = outc + ((size_t)b * Nn + i) * 3;
    atomicAdd(dst + 0, g_cdiff[e * 3 + 0] * wv);
    atomicAdd(dst + 1, g_cdiff[e * 3 + 1] * wv);
    atomicAdd(dst + 2, g_cdiff[e * 3 + 2] * wv);
}

// ---------------- launch ----------------
extern "C" void kernel_launch(void* const* d_in, const int* in_sizes, int n_in,
                              void* d_out, int out_size) {
    const float* h     = (const float*)d_in[0];
    const float* coord = (const float*)d_in[1];
    const int*   ei    = (const int*)d_in[2];
    const float* ew1   = (const float*)d_in[3];
    const float* eb1   = (const float*)d_in[4];
    const float* ew2   = (const float*)d_in[5];
    const float* eb2   = (const float*)d_in[6];
    const float* lng   = (const float*)d_in[7];
    const float* lnb   = (const float*)d_in[8];
    const float* nw1   = (const float*)d_in[9];
    const float* nb1   = (const float*)d_in[10];
    const float* nw2   = (const float*)d_in[11];
    const float* nb2   = (const float*)d_in[12];
    const float* cw1   = (const float*)d_in[13];
    const float* cb1   = (const float*)d_in[14];
    const float* cw2   = (const float*)d_in[15];

    float* out_h = (float*)d_out;
    float* out_c = out_h + (size_t)BNr * Ff;

    void *p_mid, *p_ef, *p_geo, *p_w1cat, *p_w2cat2, *p_agg, *p_nodemid, *p_wsc;
    cudaGetSymbolAddress(&p_mid,     g_mid);
    cudaGetSymbolAddress(&p_ef,      g_ef);
    cudaGetSymbolAddress(&p_geo,     g_geo);
    cudaGetSymbolAddress(&p_w1cat,   g_w1cat);
    cudaGetSymbolAddress(&p_w2cat2,  g_w2cat2);
    cudaGetSymbolAddress(&p_agg,     g_agg);
    cudaGetSymbolAddress(&p_nodemid, g_nodemid);
    cudaGetSymbolAddress(&p_wsc,     g_wsc);
    float*       midp     = (float*)p_mid;
    float*       efp      = (float*)p_ef;
    const float* geop     = (const float*)p_geo;
    const float* w1catp   = (const float*)p_w1cat;
    const float* w2cat2p  = (const float*)p_w2cat2;
    const float* aggp     = (const float*)p_agg;
    float*       nodemidp = (float*)p_nodemid;
    float*       wscp     = (float*)p_wsc;

    // init: zero agg/wsc, copy coord, build w1cat + w2cat2
    k_misc<<<(BNr * Hh + 255) / 256, 256>>>(coord, out_c, ew1, ew2);
    // geometry features per edge
    k_geo<<<BE / 256, 256>>>(coord, ei);

    // GEMM1 (gather-fused): g_mid = silu([h_i|h_k|geo] @ W1cat + b1)
    k_gemm_t<2, 1, false><<<dim3(Hh / 128, BE / 128), 256>>>(
        h, nullptr, w1catp, midp, FEATP, 0, Hh, Hh, eb1, nullptr, 0, nullptr, ei, geop);

    // GEMM2 (2-head block-diag pairs): g_ef = g_mid @ blockdiag(w2) + b2, K=128
    k_gemm_t<5, 0, true><<<dim3(Hh / 128, BE / 128), 256>>>(
        midp, nullptr, w2cat2p, efp, 128, Hh, 128, Hh, eb2, nullptr, 0, nullptr, nullptr, nullptr);

    // fused LayerNorm + agg scatter (vector red)
    k_lnscatter<<<BE / 8, 256>>>(lng, lnb, ei);

    // GEMM3 fused: wsc += silu(ef @ cw1 + cb1) . cw2
    k_gemm_t<4, 0, false><<<dim3(Hh / 128, BE / 128), 256>>>(
        efp, nullptr, cw1, nullptr, Hh, Hh, Hh, 0, cb1, cw2, 0, wscp, nullptr, nullptr);

    // coord scatter
    k_coordscatter<<<BE / 256, 256>>>(ei, out_c);

    // node MLP (input concat fused via split-A)
    k_gemm_t<2, 2, false><<<dim3(Hh / 128, BNr / 128), 256>>>(
        h, aggp, nw1, nodemidp, Hh + Ff, 0, Hh, Hh, nb1, nullptr, 0, nullptr, nullptr, nullptr);
    k_gemm_t<3, 0, false><<<dim3(Ff / 128, BNr / 128), 256>>>(
        nodemidp, nullptr, nw2, out_h, Hh, Hh, Ff, Ff, nb2, h, Ff, nullptr, nullptr, nullptr);
}

// round 7
// speedup vs baseline: 2.5568x; 1.2216x over previous
#include <cuda_runtime.h>
#include <math.h>
#include <stdint.h>

// Problem constants (fixed shapes)
#define Bc   2
#define Nn   8192
#define Ff   128
#define Ee   131072
#define Hh   256
#define NHh  4
#define Dd   64
#define FEATN 268
#define FEATP 288          // padded K for GEMM1
#define BE   (Bc*Ee)       // 262144 edge rows
#define BNr  (Bc*Nn)       // 16384 node rows

// ---------------- static scratch ----------------
static __device__ float g_ef[(size_t)BE * Hh];
static __device__ float g_geo[(size_t)BE * 32];   // 12 geometry feats + 20 zeros
static __device__ float g_cdiff[BE * 3];
static __device__ float g_wsc[BE];
static __device__ float g_agg[BNr * Hh];
static __device__ float g_nodemid[BNr * Hh];
// pre-transposed, pre-tf32 weights: BT[n][k]
static __device__ uint32_t g_w1T[Hh * FEATP];        // (256, 288)
static __device__ uint32_t g_w2T[2 * 128 * 128];     // two head-pair block-diag tiles
static __device__ uint32_t g_cw1T[Hh * Hh];          // (256, 256)
static __device__ uint32_t g_nw1T[Hh * (Hh + Ff)];   // (256, 384)
static __device__ uint32_t g_nw2T[Ff * Hh];          // (128, 256)

// ---------------- helpers ----------------
__device__ __forceinline__ uint32_t f2tf(float x) {
    uint32_t r; asm("cvt.rna.tf32.f32 %0, %1;" : "=r"(r) : "f"(x)); return r;
}
__device__ __forceinline__ void ldsm4(uint32_t& r0, uint32_t& r1, uint32_t& r2, uint32_t& r3, uint32_t a) {
    asm volatile("ldmatrix.sync.aligned.m8n8.x4.shared.b16 {%0,%1,%2,%3}, [%4];"
                 : "=r"(r0), "=r"(r1), "=r"(r2), "=r"(r3) : "r"(a));
}
__device__ __forceinline__ void mma8(float* c, const uint32_t* a, const uint32_t* b) {
    asm volatile("mma.sync.aligned.m16n8k8.row.col.f32.tf32.tf32.f32 "
                 "{%0,%1,%2,%3}, {%4,%5,%6,%7}, {%8,%9}, {%0,%1,%2,%3};"
                 : "+f"(c[0]), "+f"(c[1]), "+f"(c[2]), "+f"(c[3])
                 : "r"(a[0]), "r"(a[1]), "r"(a[2]), "r"(a[3]), "r"(b[0]), "r"(b[1]));
}
__device__ __forceinline__ float silu_f(float x) { return x / (1.f + expf(-x)); }
__device__ __forceinline__ void red4(float* addr, float4 v) {
    asm volatile("red.global.add.v4.f32 [%0], {%1,%2,%3,%4};"
                 :: "l"(addr), "f"(v.x), "f"(v.y), "f"(v.z), "f"(v.w) : "memory");
}

// ---------------- combined init ----------------
__global__ void k_misc(const float* __restrict__ coord, float* __restrict__ outc,
                       const float* __restrict__ w1, const float* __restrict__ w2,
                       const float* __restrict__ cw1, const float* __restrict__ nw1,
                       const float* __restrict__ nw2) {
    int idx = blockIdx.x * blockDim.x + threadIdx.x;
    if (idx < BNr * Hh) g_agg[idx] = 0.f;
    if (idx < BE) g_wsc[idx] = 0.f;
    if (idx < Bc * Nn * 3) outc[idx] = coord[idx];
    if (idx < Hh * FEATP) {                    // w1T[n][f] = w1[n>>6][f][n&63]
        int n = idx / FEATP, f = idx - n * FEATP;
        g_w1T[idx] = (f < FEATN) ? f2tf(w1[(((n >> 6) * FEATN) + f) * Dd + (n & 63)]) : 0u;
    }
    if (idx < 2 * 128 * 128) {                 // w2T[p][n][k] block-diag pair
        int p = idx >> 14, n = (idx >> 7) & 127, k = idx & 127;
        g_w2T[idx] = ((k >> 6) == (n >> 6))
            ? f2tf(w2[((p << 1) + (n >> 6)) * (Dd * Dd) + (k & 63) * Dd + (n & 63)]) : 0u;
    }
    if (idx < Hh * Hh) {                       // cw1T[n][k] = cw1[k][n]
        int n = idx >> 8, k = idx & 255;
        g_cw1T[idx] = f2tf(cw1[k * Hh + n]);
    }
    if (idx < Hh * (Hh + Ff)) {                // nw1T[n][k] = nw1[k][n]
        int n = idx / (Hh + Ff), k = idx - n * (Hh + Ff);
        g_nw1T[idx] = f2tf(nw1[k * Hh + n]);
    }
    if (idx < Ff * Hh) {                       // nw2T[n][k] = nw2[k][n]
        int n = idx >> 8, k = idx & 255;
        g_nw2T[idx] = f2tf(nw2[k * Ff + n]);
    }
}

// geometry features per edge (thread per edge)
__global__ void k_geo(const float* __restrict__ coord, const int* __restrict__ ei) {
    int e = blockIdx.x * blockDim.x + threadIdx.x;
    if (e >= BE) return;
    int b = (e >= Ee) ? 1 : 0, j = e - b * Ee;
    int i = ei[j], k = ei[Ee + j];
    const float* ci = coord + ((size_t)b * Nn + i) * 3;
    const float* ck = coord + ((size_t)b * Nn + k) * 3;
    float cix = ci[0], ciy = ci[1], ciz = ci[2];
    float ckx = ck[0], cky = ck[1], ckz = ck[2];
    float dx = cix - ckx, dy = ciy - cky, dz = ciz - ckz;
    float radial = dx * dx + dy * dy + dz * dz;
    float dist = sqrtf(radial);
    float dotv = cix * ckx + ciy * cky + ciz * ckz;
    float inva = 1.f / (dist + 1e-8f);
    float ax = dx * inva, ay = dy * inva, az = dz * inva;
    float crx = ciy * ckz - ciz * cky;
    float cry = ciz * ckx - cix * ckz;
    float crz = cix * cky - ciy * ckx;
    float nb = sqrtf(crx * crx + cry * cry + crz * crz);
    float invb = 1.f / (nb + 1e-8f);
    float bx = crx * invb, by = cry * invb, bz = crz * invb;
    float cx = ay * bz - az * by;
    float cy = az * bx - ax * bz;
    float cz = ax * by - ay * bx;
    float na  = sqrtf(ax * ax + ay * ay + az * az);
    float nbv = sqrtf(bx * bx + by * by + bz * bz);
    float ncv = sqrtf(cx * cx + cy * cy + cz * cz);
    bool bad = (na < 1e-6f) || (nbv < 1e-6f) || (ncv < 1e-6f);
    if (bad) { ax = 1.f; bx = 0.f; cx = 0.f;
               ay = 0.f; by = 1.f; cy = 0.f;
               az = 0.f; bz = 0.f; cz = 1.f; }
    float4* g = (float4*)(g_geo + (size_t)e * 32);
    g[0] = make_float4(radial, dist, dotv, ax);
    g[1] = make_float4(bx, cx, ay, by);
    g[2] = make_float4(cy, az, bz, cz);
    float4 z = make_float4(0.f, 0.f, 0.f, 0.f);
    g[3] = z; g[4] = z; g[5] = z; g[6] = z; g[7] = z;
    g_cdiff[e * 3 + 0] = dx;
    g_cdiff[e * 3 + 1] = dy;
    g_cdiff[e * 3 + 2] = dz;
}

// ---------------- tf32 tensor-core GEMM ----------------
// Block tile 128x128, BK=32, 8 warps (2x4), warp tile 64x32, m16n8k8 tf32 MMA.
// B comes pre-transposed + pre-tf32: BT[n][k], row-major along k.
// EPI: 2 bias+silu, 3 bias+residual, 4 bias+silu+dot(extra)->atomic wsc (no store)
// MODE: 0 normal A, 2 node-split A (h 128 | agg 256)
#define AST 36
#define BST 36
#define MST 132

template <int EPI, int MODE>
__global__ void __launch_bounds__(256) k_gemm_t(
    const float* __restrict__ A, const float* __restrict__ A2,
    const uint32_t* __restrict__ BT, float* __restrict__ C,
    int K, int lda, int ldbT, int ldc,
    const float* __restrict__ bias, const float* __restrict__ extra, int ldr,
    float* __restrict__ wsc)
{
    __shared__ __align__(16) uint32_t As[128 * AST];
    __shared__ __align__(16) uint32_t Bs[128 * BST];
    const int tid = threadIdx.x, lane = tid & 31, wid = tid >> 5;
    const int wm = wid >> 2, wn = wid & 3;
    const int m0 = blockIdx.y * 128, n0 = blockIdx.x * 128;

    const int am = tid >> 3;
    const int ak = (tid & 7) << 2;

    const uint32_t* BTg = BT + (size_t)n0 * ldbT;

    const float* pA[4]; const float* pS[4];
#pragma unroll
    for (int i = 0; i < 4; i++) {
        int r = m0 + am + 32 * i;
        if (MODE == 0) {
            pA[i] = A + (size_t)r * lda;
        } else {
            pA[i] = A + (size_t)r * 128;
            pS[i] = A2 + (size_t)r * 256;
        }
    }
    auto loadA = [&](int i, int kcol) -> float4 {
        if (MODE == 0) return *(const float4*)(pA[i] + kcol);
        if (kcol < 128) return *(const float4*)(pA[i] + kcol);
        return *(const float4*)(pS[i] + (kcol - 128));
    };

    float acc[4][4][4];
#pragma unroll
    for (int i = 0; i < 4; i++)
#pragma unroll
        for (int j = 0; j < 4; j++) { acc[i][j][0] = 0.f; acc[i][j][1] = 0.f; acc[i][j][2] = 0.f; acc[i][j][3] = 0.f; }

    float4 pa[4]; uint4 pb[4];
#pragma unroll
    for (int i = 0; i < 4; i++) {
        pa[i] = loadA(i, ak);
        pb[i] = *(const uint4*)(BTg + (size_t)(am + 32 * i) * ldbT + ak);
    }

    const uint32_t as_base = (uint32_t)__cvta_generic_to_shared(As);
    const uint32_t bs_base = (uint32_t)__cvta_generic_to_shared(Bs);
    const int a_r = wm * 64 + (lane & 15);
    const int a_q = (lane >> 4) << 2;
    const int b_r = wn * 32 + (lane & 7) + ((lane >> 4) << 3);
    const int b_q = ((lane >> 3) & 1) << 2;

    for (int k0 = 0; k0 < K; k0 += 32) {
#pragma unroll
        for (int i = 0; i < 4; i++) {
            *(uint4*)&As[(am + 32 * i) * AST + ak] =
                make_uint4(f2tf(pa[i].x), f2tf(pa[i].y), f2tf(pa[i].z), f2tf(pa[i].w));
            *(uint4*)&Bs[(am + 32 * i) * BST + ak] = pb[i];
        }
        __syncthreads();
        if (k0 + 32 < K) {
#pragma unroll
            for (int i = 0; i < 4; i++) {
                pa[i] = loadA(i, k0 + 32 + ak);
                pb[i] = *(const uint4*)(BTg + (size_t)(am + 32 * i) * ldbT + k0 + 32 + ak);
            }
        }
#pragma unroll
        for (int kk = 0; kk < 4; kk++) {
            uint32_t af[4][4], bf[4][2];
#pragma unroll
            for (int mi = 0; mi < 4; mi++)
                ldsm4(af[mi][0], af[mi][1], af[mi][2], af[mi][3],
                      as_base + (((a_r + mi * 16) * AST + kk * 8 + a_q) << 2));
#pragma unroll
            for (int np = 0; np < 2; np++) {
                uint32_t r0, r1, r2, r3;
                ldsm4(r0, r1, r2, r3,
                      bs_base + (((b_r + np * 16) * BST + kk * 8 + b_q) << 2));
                bf[np * 2][0] = r0; bf[np * 2][1] = r1;
                bf[np * 2 + 1][0] = r2; bf[np * 2 + 1][1] = r3;
            }
#pragma unroll
            for (int mi = 0; mi < 4; mi++)
#pragma unroll
                for (int ni = 0; ni < 4; ni++)
                    mma8(acc[mi][ni], af[mi], bf[ni]);
        }
        __syncthreads();
    }

    // ---------------- epilogue ----------------
    const int row0 = m0 + wm * 64 + (lane >> 2);
    const int colw = wn * 32 + ((lane & 3) << 1);
#pragma unroll
    for (int mi = 0; mi < 4; mi++) {
        float slo = 0.f, shi = 0.f;
        int r = row0 + mi * 16;
#pragma unroll
        for (int ni = 0; ni < 4; ni++) {
            int col = n0 + colw + ni * 8;
            float2 bb = *(const float2*)(bias + col);
            float v0 = acc[mi][ni][0] + bb.x, v1 = acc[mi][ni][1] + bb.y;
            float v2 = acc[mi][ni][2] + bb.x, v3 = acc[mi][ni][3] + bb.y;
            if (EPI == 2 || EPI == 4) {
                v0 = silu_f(v0); v1 = silu_f(v1); v2 = silu_f(v2); v3 = silu_f(v3);
            }
            if (EPI == 3) {
                float2 ra = *(const float2*)(extra + (size_t)r * ldr + col);
                float2 rb = *(const float2*)(extra + (size_t)(r + 8) * ldr + col);
                v0 += ra.x; v1 += ra.y; v2 += rb.x; v3 += rb.y;
            }
            if (EPI == 4) {
                float2 w = *(const float2*)(extra + col);
                slo += v0 * w.x + v1 * w.y;
                shi += v2 * w.x + v3 * w.y;
            } else {
                *(float2*)(C + (size_t)r * ldc + col)       = make_float2(v0, v1);
                *(float2*)(C + (size_t)(r + 8) * ldc + col) = make_float2(v2, v3);
            }
        }
        if (EPI == 4) {
            slo += __shfl_xor_sync(0xffffffffu, slo, 1);
            slo += __shfl_xor_sync(0xffffffffu, slo, 2);
            shi += __shfl_xor_sync(0xffffffffu, shi, 1);
            shi += __shfl_xor_sync(0xffffffffu, shi, 2);
            if ((lane & 3) == 0) {
                atomicAdd(wsc + r, slo);
                atomicAdd(wsc + r + 8, shi);
            }
        }
    }
}

// ---------------- fused GEMM1+GEMM2 ----------------
// stage1: mid = silu([h_i|h_k|geo] @ w1T + b1)  (K=288), kept as tf32 in smem
// stage2: ef  = mid @ w2T_pair + b2             (K=128, A from smem)
__global__ void __launch_bounds__(256) k_gemm12(
    const float* __restrict__ h, const uint32_t* __restrict__ w1T,
    const uint32_t* __restrict__ w2T, float* __restrict__ ef,
    const int* __restrict__ ei, const float* __restrict__ geo,
    const float* __restrict__ b1, const float* __restrict__ b2)
{
    extern __shared__ uint32_t sm[];
    uint32_t* As = sm;                       // 128*AST
    uint32_t* Bs = sm + 128 * AST;           // 128*BST
    uint32_t* Ms = sm + 128 * (AST + BST);   // 128*MST
    const int tid = threadIdx.x, lane = tid & 31, wid = tid >> 5;
    const int wm = wid >> 2, wn = wid & 3;
    const int m0 = blockIdx.y * 128, n0 = blockIdx.x * 128;

    const int am = tid >> 3;
    const int ak = (tid & 7) << 2;

    const uint32_t* BTg = w1T + (size_t)n0 * FEATP;

    const float* pA[4]; const float* pS[4]; const float* pG[4];
    {
        int b = (m0 >= Ee) ? 1 : 0;
#pragma unroll
        for (int i = 0; i < 4; i++) {
            int r = m0 + am + 32 * i;
            int j = r - b * Ee;
            pA[i] = h + ((size_t)b * Nn + ei[j]) * Ff;
            pS[i] = h + ((size_t)b * Nn + ei[Ee + j]) * Ff;
            pG[i] = geo + (size_t)r * 32;
        }
    }
    auto loadA = [&](int i, int kcol) -> float4 {
        if (kcol < 128) return *(const float4*)(pA[i] + kcol);
        if (kcol < 256) return *(const float4*)(pS[i] + (kcol - 128));
        return *(const float4*)(pG[i] + (kcol - 256));
    };

    float acc[4][4][4];
#pragma unroll
    for (int i = 0; i < 4; i++)
#pragma unroll
        for (int j = 0; j < 4; j++) { acc[i][j][0] = 0.f; acc[i][j][1] = 0.f; acc[i][j][2] = 0.f; acc[i][j][3] = 0.f; }

    float4 pa[4]; uint4 pb[4];
#pragma unroll
    for (int i = 0; i < 4; i++) {
        pa[i] = loadA(i, ak);
        pb[i] = *(const uint4*)(BTg + (size_t)(am + 32 * i) * FEATP + ak);
    }

    const uint32_t as_base = (uint32_t)__cvta_generic_to_shared(As);
    const uint32_t bs_base = (uint32_t)__cvta_generic_to_shared(Bs);
    const uint32_t ms_base = (uint32_t)__cvta_generic_to_shared(Ms);
    const int a_r = wm * 64 + (lane & 15);
    const int a_q = (lane >> 4) << 2;
    const int b_r = wn * 32 + (lane & 7) + ((lane >> 4) << 3);
    const int b_q = ((lane >> 3) & 1) << 2;

    // ---- stage 1 mainloop, K=288 ----
    for (int k0 = 0; k0 < FEATP; k0 += 32) {
#pragma unroll
        for (int i = 0; i < 4; i++) {
            *(uint4*)&As[(am + 32 * i) * AST + ak] =
                make_uint4(f2tf(pa[i].x), f2tf(pa[i].y), f2tf(pa[i].z), f2tf(pa[i].w));
            *(uint4*)&Bs[(am + 32 * i) * BST + ak] = pb[i];
        }
        __syncthreads();
        if (k0 + 32 < FEATP) {
#pragma unroll
            for (int i = 0; i < 4; i++) {
                pa[i] = loadA(i, k0 + 32 + ak);
                pb[i] = *(const uint4*)(BTg + (size_t)(am + 32 * i) * FEATP + k0 + 32 + ak);
            }
        }
#pragma unroll
        for (int kk = 0; kk < 4; kk++) {
            uint32_t af[4][4], bf[4][2];
#pragma unroll
            for (int mi = 0; mi < 4; mi++)
                ldsm4(af[mi][0], af[mi][1], af[mi][2], af[mi][3],
                      as_base + (((a_r + mi * 16) * AST + kk * 8 + a_q) << 2));
#pragma unroll
            for (int np = 0; np < 2; np++) {
                uint32_t r0, r1, r2, r3;
                ldsm4(r0, r1, r2, r3,
                      bs_base + (((b_r + np * 16) * BST + kk * 8 + b_q) << 2));
                bf[np * 2][0] = r0; bf[np * 2][1] = r1;
                bf[np * 2 + 1][0] = r2; bf[np * 2 + 1][1] = r3;
            }
#pragma unroll
            for (int mi = 0; mi < 4; mi++)
#pragma unroll
                for (int ni = 0; ni < 4; ni++)
                    mma8(acc[mi][ni], af[mi], bf[ni]);
        }
        __syncthreads();
    }

    // ---- epilogue 1: silu + bias -> Ms (tf32), reset acc ----
    const int lrow0 = wm * 64 + (lane >> 2);
    const int lcolw = wn * 32 + ((lane & 3) << 1);
#pragma unroll
    for (int mi = 0; mi < 4; mi++) {
        int r = lrow0 + mi * 16;
#pragma unroll
        for (int ni = 0; ni < 4; ni++) {
            int col = lcolw + ni * 8;
            float2 bb = *(const float2*)(b1 + n0 + col);
            float v0 = silu_f(acc[mi][ni][0] + bb.x);
            float v1 = silu_f(acc[mi][ni][1] + bb.y);
            float v2 = silu_f(acc[mi][ni][2] + bb.x);
            float v3 = silu_f(acc[mi][ni][3] + bb.y);
            *(uint2*)&Ms[r * MST + col]       = make_uint2(f2tf(v0), f2tf(v1));
            *(uint2*)&Ms[(r + 8) * MST + col] = make_uint2(f2tf(v2), f2tf(v3));
            acc[mi][ni][0] = 0.f; acc[mi][ni][1] = 0.f;
            acc[mi][ni][2] = 0.f; acc[mi][ni][3] = 0.f;
        }
    }

    // ---- stage 2 mainloop, K=128, A from Ms, B = w2 pair tile ----
    const uint32_t* W2 = w2T + (size_t)blockIdx.x * (128 * 128);
    for (int k0 = 0; k0 < 128; k0 += 32) {
#pragma unroll
        for (int i = 0; i < 4; i++)
            *(uint4*)&Bs[(am + 32 * i) * BST + ak] =
                *(const uint4*)(W2 + (size_t)(am + 32 * i) * 128 + k0 + ak);
        __syncthreads();
#pragma unroll
        for (int kk = 0; kk < 4; kk++) {
            uint32_t af[4][4], bf[4][2];
#pragma unroll
            for (int mi = 0; mi < 4; mi++)
                ldsm4(af[mi][0], af[mi][1], af[mi][2], af[mi][3],
                      ms_base + (((a_r + mi * 16) * MST + k0 + kk * 8 + a_q) << 2));
#pragma unroll
            for (int np = 0; np < 2; np++) {
                uint32_t r0, r1, r2, r3;
                ldsm4(r0, r1, r2, r3,
                      bs_base + (((b_r + np * 16) * BST + kk * 8 + b_q) << 2));
                bf[np * 2][0] = r0; bf[np * 2][1] = r1;
                bf[np * 2 + 1][0] = r2; bf[np * 2 + 1][1] = r3;
            }
#pragma unroll
            for (int mi = 0; mi < 4; mi++)
#pragma unroll
                for (int ni = 0; ni < 4; ni++)
                    mma8(acc[mi][ni], af[mi], bf[ni]);
        }
        __syncthreads();
    }

    // ---- epilogue 2: + b2, store f32 to ef ----
#pragma unroll
    for (int mi = 0; mi < 4; mi++) {
        int r = m0 + lrow0 + mi * 16;
#pragma unroll
        for (int ni = 0; ni < 4; ni++) {
            int col = n0 + lcolw + ni * 8;
            float2 bb = *(const float2*)(b2 + col);
            *(float2*)(ef + (size_t)r * Hh + col) =
                make_float2(acc[mi][ni][0] + bb.x, acc[mi][ni][1] + bb.y);
            *(float2*)(ef + (size_t)(r + 8) * Hh + col) =
                make_float2(acc[mi][ni][2] + bb.x, acc[mi][ni][3] + bb.y);
        }
    }
}

// Fused LayerNorm (in-place on g_ef) + agg segment-sum. One warp per edge.
__global__ void k_lnscatter(const float* __restrict__ gam, const float* __restrict__ bet,
                            const int* __restrict__ ei) {
    int wid = blockIdx.x * (blockDim.x >> 5) + (threadIdx.x >> 5);
    int lane = threadIdx.x & 31;
    if (wid >= BE) return;
    float* row = g_ef + (size_t)wid * Hh;
    float4 x0 = ((float4*)row)[lane];
    float4 x1 = ((float4*)row)[lane + 32];
    float s  = x0.x + x0.y + x0.z + x0.w + x1.x + x1.y + x1.z + x1.w;
    float ss = x0.x*x0.x + x0.y*x0.y + x0.z*x0.z + x0.w*x0.w
             + x1.x*x1.x + x1.y*x1.y + x1.z*x1.z + x1.w*x1.w;
#pragma unroll
    for (int o = 16; o; o >>= 1) {
        s  += __shfl_xor_sync(0xffffffffu, s,  o);
        ss += __shfl_xor_sync(0xffffffffu, ss, o);
    }
    float mu  = s * (1.f / 256.f);
    float var = ss * (1.f / 256.f) - mu * mu;
    float rstd = rsqrtf(var + 1e-5f);
    float4 g0 = ((const float4*)gam)[lane], g1 = ((const float4*)gam)[lane + 32];
    float4 b0 = ((const float4*)bet)[lane], b1 = ((const float4*)bet)[lane + 32];
    x0.x = (x0.x - mu) * rstd * g0.x + b0.x;
    x0.y = (x0.y - mu) * rstd * g0.y + b0.y;
    x0.z = (x0.z - mu) * rstd * g0.z + b0.z;
    x0.w = (x0.w - mu) * rstd * g0.w + b0.w;
    x1.x = (x1.x - mu) * rstd * g1.x + b1.x;
    x1.y = (x1.y - mu) * rstd * g1.y + b1.y;
    x1.z = (x1.z - mu) * rstd * g1.z + b1.z;
    x1.w = (x1.w - mu) * rstd * g1.w + b1.w;
    ((float4*)row)[lane]      = x0;
    ((float4*)row)[lane + 32] = x1;
    int b = (wid >= Ee) ? 1 : 0, j = wid - b * Ee;
    int i = ei[j];
    float* arow = g_agg + ((size_t)b * Nn + i) * Hh;
    red4(arow + 4 * lane, x0);
    red4(arow + 128 + 4 * lane, x1);
}

// coord scatter: thread per edge
__global__ void k_coordscatter(const int* __restrict__ ei, float* __restrict__ outc) {
    int e = blockIdx.x * blockDim.x + threadIdx.x;
    if (e >= BE) return;
    int b = (e >= Ee) ? 1 : 0, j = e - b * Ee;
    int i = ei[j];
    float wv = g_wsc[e];
    float* dst = outc + ((size_t)b * Nn + i) * 3;
    atomicAdd(dst + 0, g_cdiff[e * 3 + 0] * wv);
    atomicAdd(dst + 1, g_cdiff[e * 3 + 1] * wv);
    atomicAdd(dst + 2, g_cdiff[e * 3 + 2] * wv);
}

// ---------------- launch ----------------
extern "C" void kernel_launch(void* const* d_in, const int* in_sizes, int n_in,
                              void* d_out, int out_size) {
    const float* h     = (const float*)d_in[0];
    const float* coord = (const float*)d_in[1];
    const int*   ei    = (const int*)d_in[2];
    const float* ew1   = (const float*)d_in[3];
    const float* eb1   = (const float*)d_in[4];
    const float* ew2   = (const float*)d_in[5];
    const float* eb2   = (const float*)d_in[6];
    const float* lng   = (const float*)d_in[7];
    const float* lnb   = (const float*)d_in[8];
    const float* nw1   = (const float*)d_in[9];
    const float* nb1   = (const float*)d_in[10];
    const float* nw2   = (const float*)d_in[11];
    const float* nb2   = (const float*)d_in[12];
    const float* cw1   = (const float*)d_in[13];
    const float* cb1   = (const float*)d_in[14];
    const float* cw2   = (const float*)d_in[15];

    float* out_h = (float*)d_out;
    float* out_c = out_h + (size_t)BNr * Ff;

    void *p_ef, *p_geo, *p_w1T, *p_w2T, *p_cw1T, *p_nw1T, *p_nw2T, *p_agg, *p_nodemid, *p_wsc;
    cudaGetSymbolAddress(&p_ef,      g_ef);
    cudaGetSymbolAddress(&p_geo,     g_geo);
    cudaGetSymbolAddress(&p_w1T,     g_w1T);
    cudaGetSymbolAddress(&p_w2T,     g_w2T);
    cudaGetSymbolAddress(&p_cw1T,    g_cw1T);
    cudaGetSymbolAddress(&p_nw1T,    g_nw1T);
    cudaGetSymbolAddress(&p_nw2T,    g_nw2T);
    cudaGetSymbolAddress(&p_agg,     g_agg);
    cudaGetSymbolAddress(&p_nodemid, g_nodemid);
    cudaGetSymbolAddress(&p_wsc,     g_wsc);
    float*          efp      = (float*)p_ef;
    const float*    geop     = (const float*)p_geo;
    const uint32_t* w1Tp     = (const uint32_t*)p_w1T;
    const uint32_t* w2Tp     = (const uint32_t*)p_w2T;
    const uint32_t* cw1Tp    = (const uint32_t*)p_cw1T;
    const uint32_t* nw1Tp    = (const uint32_t*)p_nw1T;
    const uint32_t* nw2Tp    = (const uint32_t*)p_nw2T;
    const float*    aggp     = (const float*)p_agg;
    float*          nodemidp = (float*)p_nodemid;
    float*          wscp     = (float*)p_wsc;

    const int smem12 = 128 * (AST + BST + MST) * 4;   // ~104.4 KB
    cudaFuncSetAttribute(k_gemm12, cudaFuncAttributeMaxDynamicSharedMemorySize, smem12);

    // init + weights transform
    k_misc<<<(BNr * Hh + 255) / 256, 256>>>(coord, out_c, ew1, ew2, cw1, nw1, nw2);
    k_geo<<<BE / 256, 256>>>(coord, ei);

    // fused GEMM1+GEMM2: ef = silu([h_i|h_k|geo]@w1+b1) @ blockdiag(w2) + b2
    k_gemm12<<<dim3(2, BE / 128), 256, smem12>>>(h, w1Tp, w2Tp, efp, ei, geop, eb1, eb2);

    // fused LayerNorm + agg scatter
    k_lnscatter<<<BE / 8, 256>>>(lng, lnb, ei);

    // GEMM3 fused: wsc += silu(ef @ cw1 + cb1) . cw2
    k_gemm_t<4, 0><<<dim3(2, BE / 128), 256>>>(
        efp, nullptr, cw1Tp, nullptr, Hh, Hh, Hh, 0, cb1, cw2, 0, wscp);

    // coord scatter
    k_coordscatter<<<BE / 256, 256>>>(ei, out_c);

    // node MLP (input concat fused via split-A)
    k_gemm_t<2, 2><<<dim3(2, BNr / 128), 256>>>(
        h, aggp, nw1Tp, nodemidp, Hh + Ff, 0, Hh + Ff, Hh, nb1, nullptr, 0, nullptr);
    k_gemm_t<3, 0><<<dim3(1, BNr / 128), 256>>>(
        nodemidp, nullptr, nw2Tp, out_h, Hh, Hh, Hh, Ff, nb2, h, Ff, nullptr);
}

// round 10
// speedup vs baseline: 2.6878x; 1.0512x over previous
#include <cuda_runtime.h>
#include <math.h>
#include <stdint.h>

// Problem constants (fixed shapes)
#define Bc   2
#define Nn   8192
#define Ff   128
#define Ee   131072
#define Hh   256
#define NHh  4
#define Dd   64
#define FEATN 268
#define FEATP 288          // padded K for GEMM1
#define BE   (Bc*Ee)       // 262144 edge rows
#define BNr  (Bc*Nn)       // 16384 node rows

// ---------------- static scratch ----------------
static __device__ float g_ef[(size_t)BE * Hh];     // raw (pre-LN) edge features
static __device__ float g_stats[(size_t)BE * 2];   // per row: sum, sumsq (atomic-accumulated)
static __device__ float g_geo[(size_t)BE * 32];
static __device__ float g_cdiff[BE * 3];
static __device__ float g_wsc[BE];
static __device__ float g_agg[BNr * Hh];
static __device__ float g_nodemid[BNr * Hh];
// pre-transposed, pre-tf32 weights: BT[n][k]
static __device__ uint32_t g_w1T[Hh * FEATP];
static __device__ uint32_t g_w2T[2 * 128 * 128];
static __device__ uint32_t g_cw1T[Hh * Hh];
static __device__ uint32_t g_nw1T[Hh * (Hh + Ff)];
static __device__ uint32_t g_nw2T[Ff * Hh];

// ---------------- helpers ----------------
__device__ __forceinline__ uint32_t f2tf(float x) {
    uint32_t r; asm("cvt.rna.tf32.f32 %0, %1;" : "=r"(r) : "f"(x)); return r;
}
__device__ __forceinline__ void ldsm4(uint32_t& r0, uint32_t& r1, uint32_t& r2, uint32_t& r3, uint32_t a) {
    asm volatile("ldmatrix.sync.aligned.m8n8.x4.shared.b16 {%0,%1,%2,%3}, [%4];"
                 : "=r"(r0), "=r"(r1), "=r"(r2), "=r"(r3) : "r"(a));
}
__device__ __forceinline__ void mma8(float* c, const uint32_t* a, const uint32_t* b) {
    asm volatile("mma.sync.aligned.m16n8k8.row.col.f32.tf32.tf32.f32 "
                 "{%0,%1,%2,%3}, {%4,%5,%6,%7}, {%8,%9}, {%0,%1,%2,%3};"
                 : "+f"(c[0]), "+f"(c[1]), "+f"(c[2]), "+f"(c[3])
                 : "r"(a[0]), "r"(a[1]), "r"(a[2]), "r"(a[3]), "r"(b[0]), "r"(b[1]));
}
__device__ __forceinline__ float silu_f(float x) { return x / (1.f + expf(-x)); }
__device__ __forceinline__ void red4(float* addr, float4 v) {
    asm volatile("red.global.add.v4.f32 [%0], {%1,%2,%3,%4};"
                 :: "l"(addr), "f"(v.x), "f"(v.y), "f"(v.z), "f"(v.w) : "memory");
}

// ---------------- combined init ----------------
__global__ void k_misc(const float* __restrict__ coord, float* __restrict__ outc,
                       const float* __restrict__ w1, const float* __restrict__ w2,
                       const float* __restrict__ cw1, const float* __restrict__ nw1,
                       const float* __restrict__ nw2) {
    int idx = blockIdx.x * blockDim.x + threadIdx.x;
    if (idx < BNr * Hh) g_agg[idx] = 0.f;
    if (idx < BE) g_wsc[idx] = 0.f;
    if (idx < BE * 2) g_stats[idx] = 0.f;
    if (idx < Bc * Nn * 3) outc[idx] = coord[idx];
    if (idx < Hh * FEATP) {
        int n = idx / FEATP, f = idx - n * FEATP;
        g_w1T[idx] = (f < FEATN) ? f2tf(w1[(((n >> 6) * FEATN) + f) * Dd + (n & 63)]) : 0u;
    }
    if (idx < 2 * 128 * 128) {
        int p = idx >> 14, n = (idx >> 7) & 127, k = idx & 127;
        g_w2T[idx] = ((k >> 6) == (n >> 6))
            ? f2tf(w2[((p << 1) + (n >> 6)) * (Dd * Dd) + (k & 63) * Dd + (n & 63)]) : 0u;
    }
    if (idx < Hh * Hh) {
        int n = idx >> 8, k = idx & 255;
        g_cw1T[idx] = f2tf(cw1[k * Hh + n]);
    }
    if (idx < Hh * (Hh + Ff)) {
        int n = idx / (Hh + Ff), k = idx - n * (Hh + Ff);
        g_nw1T[idx] = f2tf(nw1[k * Hh + n]);
    }
    if (idx < Ff * Hh) {
        int n = idx >> 8, k = idx & 255;
        g_nw2T[idx] = f2tf(nw2[k * Ff + n]);
    }
}

// geometry features per edge (thread per edge)
__global__ void k_geo(const float* __restrict__ coord, const int* __restrict__ ei) {
    int e = blockIdx.x * blockDim.x + threadIdx.x;
    if (e >= BE) return;
    int b = (e >= Ee) ? 1 : 0, j = e - b * Ee;
    int i = ei[j], k = ei[Ee + j];
    const float* ci = coord + ((size_t)b * Nn + i) * 3;
    const float* ck = coord + ((size_t)b * Nn + k) * 3;
    float cix = ci[0], ciy = ci[1], ciz = ci[2];
    float ckx = ck[0], cky = ck[1], ckz = ck[2];
    float dx = cix - ckx, dy = ciy - cky, dz = ciz - ckz;
    float radial = dx * dx + dy * dy + dz * dz;
    float dist = sqrtf(radial);
    float dotv = cix * ckx + ciy * cky + ciz * ckz;
    float inva = 1.f / (dist + 1e-8f);
    float ax = dx * inva, ay = dy * inva, az = dz * inva;
    float crx = ciy * ckz - ciz * cky;
    float cry = ciz * ckx - cix * ckz;
    float crz = cix * cky - ciy * ckx;
    float nb = sqrtf(crx * crx + cry * cry + crz * crz);
    float invb = 1.f / (nb + 1e-8f);
    float bx = crx * invb, by = cry * invb, bz = crz * invb;
    float cx = ay * bz - az * by;
    float cy = az * bx - ax * bz;
    float cz = ax * by - ay * bx;
    float na  = sqrtf(ax * ax + ay * ay + az * az);
    float nbv = sqrtf(bx * bx + by * by + bz * bz);
    float ncv = sqrtf(cx * cx + cy * cy + cz * cz);
    bool bad = (na < 1e-6f) || (nbv < 1e-6f) || (ncv < 1e-6f);
    if (bad) { ax = 1.f; bx = 0.f; cx = 0.f;
               ay = 0.f; by = 1.f; cy = 0.f;
               az = 0.f; bz = 0.f; cz = 1.f; }
    float4* g = (float4*)(g_geo + (size_t)e * 32);
    g[0] = make_float4(radial, dist, dotv, ax);
    g[1] = make_float4(bx, cx, ay, by);
    g[2] = make_float4(cy, az, bz, cz);
    float4 z = make_float4(0.f, 0.f, 0.f, 0.f);
    g[3] = z; g[4] = z; g[5] = z; g[6] = z; g[7] = z;
    g_cdiff[e * 3 + 0] = dx;
    g_cdiff[e * 3 + 1] = dy;
    g_cdiff[e * 3 + 2] = dz;
}

// ---------------- tf32 tensor-core GEMM (double-buffered smem) ----------------
// Block tile 128x128, BK=32, 8 warps (2x4), warp tile 64x32.
// EPI: 2 bias+silu, 3 bias+residual, 4 bias+silu+dot(extra)->atomic wsc (no store)
// MODE: 0 normal A, 2 node-split A (h 128 | agg 256), 3 A with inline LayerNorm (stats/gam/bet)
#define AST 36
#define BST 36
#define MST 132
#define GT_BUF (128 * (AST + BST))
#define GT_SMEM (2 * GT_BUF * 4)

template <int EPI, int MODE>
__global__ void __launch_bounds__(256, 2) k_gemm_t(
    const float* __restrict__ A, const float* __restrict__ A2,
    const uint32_t* __restrict__ BT, float* __restrict__ C,
    int K, int lda, int ldbT, int ldc,
    const float* __restrict__ bias, const float* __restrict__ extra, int ldr,
    float* __restrict__ wsc, const float* __restrict__ stats,
    const float* __restrict__ gam, const float* __restrict__ bet)
{
    extern __shared__ uint32_t smbuf[];
    const int tid = threadIdx.x, lane = tid & 31, wid = tid >> 5;
    const int wm = wid >> 2, wn = wid & 3;
    const int m0 = blockIdx.y * 128, n0 = blockIdx.x * 128;

    const int am = tid >> 3;
    const int ak = (tid & 7) << 2;

    const uint32_t* BTg = BT + (size_t)n0 * ldbT;

    const float* pA[4]; const float* pS[4];
    float mu_r[4], rs_r[4];
#pragma unroll
    for (int i = 0; i < 4; i++) {
        int r = m0 + am + 32 * i;
        if (MODE == 2) {
            pA[i] = A + (size_t)r * 128;
            pS[i] = A2 + (size_t)r * 256;
        } else {
            pA[i] = A + (size_t)r * lda;
        }
        if (MODE == 3) {
            float2 st = *(const float2*)(stats + 2 * (size_t)r);
            float mu = st.x * (1.f / 256.f);
            float var = st.y * (1.f / 256.f) - mu * mu;
            mu_r[i] = mu;
            rs_r[i] = rsqrtf(var + 1e-5f);
        }
    }
    auto loadA = [&](int i, int kcol) -> float4 {
        if (MODE == 2) {
            if (kcol < 128) return *(const float4*)(pA[i] + kcol);
            return *(const float4*)(pS[i] + (kcol - 128));
        }
        return *(const float4*)(pA[i] + kcol);
    };

    float acc[4][4][4];
#pragma unroll
    for (int i = 0; i < 4; i++)
#pragma unroll
        for (int j = 0; j < 4; j++) { acc[i][j][0] = 0.f; acc[i][j][1] = 0.f; acc[i][j][2] = 0.f; acc[i][j][3] = 0.f; }

    float4 pa[4]; uint4 pb[4];
#pragma unroll
    for (int i = 0; i < 4; i++) {
        pa[i] = loadA(i, ak);
        pb[i] = *(const uint4*)(BTg + (size_t)(am + 32 * i) * ldbT + ak);
    }

    const uint32_t as_base = (uint32_t)__cvta_generic_to_shared(smbuf);
    const uint32_t bs_base = as_base + 128 * AST * 4;
    const int a_r = wm * 64 + (lane & 15);
    const int a_q = (lane >> 4) << 2;
    const int b_r = wn * 32 + (lane & 7) + ((lane >> 4) << 3);
    const int b_q = ((lane >> 3) & 1) << 2;

    auto storeTiles = [&](int p, int kbase) {
        uint32_t* Ab = smbuf + p * GT_BUF;
        uint32_t* Bb = Ab + 128 * AST;
        float4 gm4, bt4;
        if (MODE == 3) {
            gm4 = *(const float4*)(gam + kbase + ak);
            bt4 = *(const float4*)(bet + kbase + ak);
        }
#pragma unroll
        for (int i = 0; i < 4; i++) {
            float4 v = pa[i];
            if (MODE == 3) {
                v.x = (v.x - mu_r[i]) * rs_r[i] * gm4.x + bt4.x;
                v.y = (v.y - mu_r[i]) * rs_r[i] * gm4.y + bt4.y;
                v.z = (v.z - mu_r[i]) * rs_r[i] * gm4.z + bt4.z;
                v.w = (v.w - mu_r[i]) * rs_r[i] * gm4.w + bt4.w;
            }
            *(uint4*)&Ab[(am + 32 * i) * AST + ak] =
                make_uint4(f2tf(v.x), f2tf(v.y), f2tf(v.z), f2tf(v.w));
            *(uint4*)&Bb[(am + 32 * i) * BST + ak] = pb[i];
        }
    };

    storeTiles(0, 0);
    __syncthreads();

    int p = 0;
    for (int k0 = 0; k0 < K; k0 += 32) {
        bool more = (k0 + 32 < K);
        if (more) {
#pragma unroll
            for (int i = 0; i < 4; i++) {
                pa[i] = loadA(i, k0 + 32 + ak);
                pb[i] = *(const uint4*)(BTg + (size_t)(am + 32 * i) * ldbT + k0 + 32 + ak);
            }
        }
        const uint32_t ab = as_base + p * (GT_BUF * 4);
        const uint32_t bb = bs_base + p * (GT_BUF * 4);
#pragma unroll
        for (int kk = 0; kk < 4; kk++) {
            uint32_t af[4][4], bf[4][2];
#pragma unroll
            for (int mi = 0; mi < 4; mi++)
                ldsm4(af[mi][0], af[mi][1], af[mi][2], af[mi][3],
                      ab + (((a_r + mi * 16) * AST + kk * 8 + a_q) << 2));
#pragma unroll
            for (int np = 0; np < 2; np++) {
                uint32_t r0, r1, r2, r3;
                ldsm4(r0, r1, r2, r3,
                      bb + (((b_r + np * 16) * BST + kk * 8 + b_q) << 2));
                bf[np * 2][0] = r0; bf[np * 2][1] = r1;
                bf[np * 2 + 1][0] = r2; bf[np * 2 + 1][1] = r3;
            }
#pragma unroll
            for (int mi = 0; mi < 4; mi++)
#pragma unroll
                for (int ni = 0; ni < 4; ni++)
                    mma8(acc[mi][ni], af[mi], bf[ni]);
        }
        if (more) storeTiles(p ^ 1, k0 + 32);
        __syncthreads();
        p ^= 1;
    }

    // ---------------- epilogue ----------------
    const int row0 = m0 + wm * 64 + (lane >> 2);
    const int colw = wn * 32 + ((lane & 3) << 1);
#pragma unroll
    for (int mi = 0; mi < 4; mi++) {
        float slo = 0.f, shi = 0.f;
        int r = row0 + mi * 16;
#pragma unroll
        for (int ni = 0; ni < 4; ni++) {
            int col = n0 + colw + ni * 8;
            float2 bb = *(const float2*)(bias + col);
            float v0 = acc[mi][ni][0] + bb.x, v1 = acc[mi][ni][1] + bb.y;
            float v2 = acc[mi][ni][2] + bb.x, v3 = acc[mi][ni][3] + bb.y;
            if (EPI == 2 || EPI == 4) {
                v0 = silu_f(v0); v1 = silu_f(v1); v2 = silu_f(v2); v3 = silu_f(v3);
            }
            if (EPI == 3) {
                float2 ra = *(const float2*)(extra + (size_t)r * ldr + col);
                float2 rb = *(const float2*)(extra + (size_t)(r + 8) * ldr + col);
                v0 += ra.x; v1 += ra.y; v2 += rb.x; v3 += rb.y;
            }
            if (EPI == 4) {
                float2 w = *(const float2*)(extra + col);
                slo += v0 * w.x + v1 * w.y;
                shi += v2 * w.x + v3 * w.y;
            } else {
                *(float2*)(C + (size_t)r * ldc + col)       = make_float2(v0, v1);
                *(float2*)(C + (size_t)(r + 8) * ldc + col) = make_float2(v2, v3);
            }
        }
        if (EPI == 4) {
            slo += __shfl_xor_sync(0xffffffffu, slo, 1);
            slo += __shfl_xor_sync(0xffffffffu, slo, 2);
            shi += __shfl_xor_sync(0xffffffffu, shi, 1);
            shi += __shfl_xor_sync(0xffffffffu, shi, 2);
            if ((lane & 3) == 0) {
                atomicAdd(wsc + r, slo);
                atomicAdd(wsc + r + 8, shi);
            }
        }
    }
}

// ---------------- fused GEMM1+GEMM2 (+LN partial stats via atomics) ----------------
__global__ void __launch_bounds__(256) k_gemm12(
    const float* __restrict__ h, const uint32_t* __restrict__ w1T,
    const uint32_t* __restrict__ w2T, float* __restrict__ ef,
    const int* __restrict__ ei, const float* __restrict__ geo,
    const float* __restrict__ b1, const float* __restrict__ b2,
    float* __restrict__ stats)
{
    extern __shared__ uint32_t sm[];
    uint32_t* As = sm;
    uint32_t* Bs = sm + 128 * AST;
    uint32_t* Ms = sm + 128 * (AST + BST);
    const int tid = threadIdx.x, lane = tid & 31, wid = tid >> 5;
    const int wm = wid >> 2, wn = wid & 3;
    const int m0 = blockIdx.y * 128, n0 = blockIdx.x * 128;

    const int am = tid >> 3;
    const int ak = (tid & 7) << 2;

    const uint32_t* BTg = w1T + (size_t)n0 * FEATP;

    const float* pA[4]; const float* pS[4]; const float* pG[4];
    {
        int b = (m0 >= Ee) ? 1 : 0;
#pragma unroll
        for (int i = 0; i < 4; i++) {
            int r = m0 + am + 32 * i;
            int j = r - b * Ee;
            pA[i] = h + ((size_t)b * Nn + ei[j]) * Ff;
            pS[i] = h + ((size_t)b * Nn + ei[Ee + j]) * Ff;
            pG[i] = geo + (size_t)r * 32;
        }
    }
    auto loadA = [&](int i, int kcol) -> float4 {
        if (kcol < 128) return *(const float4*)(pA[i] + kcol);
        if (kcol < 256) return *(const float4*)(pS[i] + (kcol - 128));
        return *(const float4*)(pG[i] + (kcol - 256));
    };

    float acc[4][4][4];
#pragma unroll
    for (int i = 0; i < 4; i++)
#pragma unroll
        for (int j = 0; j < 4; j++) { acc[i][j][0] = 0.f; acc[i][j][1] = 0.f; acc[i][j][2] = 0.f; acc[i][j][3] = 0.f; }

    float4 pa[4]; uint4 pb[4];
#pragma unroll
    for (int i = 0; i < 4; i++) {
        pa[i] = loadA(i, ak);
        pb[i] = *(const uint4*)(BTg + (size_t)(am + 32 * i) * FEATP + ak);
    }

    const uint32_t as_base = (uint32_t)__cvta_generic_to_shared(As);
    const uint32_t bs_base = (uint32_t)__cvta_generic_to_shared(Bs);
    const uint32_t ms_base = (uint32_t)__cvta_generic_to_shared(Ms);
    const int a_r = wm * 64 + (lane & 15);
    const int a_q = (lane >> 4) << 2;
    const int b_r = wn * 32 + (lane & 7) + ((lane >> 4) << 3);
    const int b_q = ((lane >> 3) & 1) << 2;

    // ---- stage 1 mainloop, K=288 ----
    for (int k0 = 0; k0 < FEATP; k0 += 32) {
#pragma unroll
        for (int i = 0; i < 4; i++) {
            *(uint4*)&As[(am + 32 * i) * AST + ak] =
                make_uint4(f2tf(pa[i].x), f2tf(pa[i].y), f2tf(pa[i].z), f2tf(pa[i].w));
            *(uint4*)&Bs[(am + 32 * i) * BST + ak] = pb[i];
        }
        __syncthreads();
        if (k0 + 32 < FEATP) {
#pragma unroll
            for (int i = 0; i < 4; i++) {
                pa[i] = loadA(i, k0 + 32 + ak);
                pb[i] = *(const uint4*)(BTg + (size_t)(am + 32 * i) * FEATP + k0 + 32 + ak);
            }
        }
#pragma unroll
        for (int kk = 0; kk < 4; kk++) {
            uint32_t af[4][4], bf[4][2];
#pragma unroll
            for (int mi = 0; mi < 4; mi++)
                ldsm4(af[mi][0], af[mi][1], af[mi][2], af[mi][3],
                      as_base + (((a_r + mi * 16) * AST + kk * 8 + a_q) << 2));
#pragma unroll
            for (int np = 0; np < 2; np++) {
                uint32_t r0, r1, r2, r3;
                ldsm4(r0, r1, r2, r3,
                      bs_base + (((b_r + np * 16) * BST + kk * 8 + b_q) << 2));
                bf[np * 2][0] = r0; bf[np * 2][1] = r1;
                bf[np * 2 + 1][0] = r2; bf[np * 2 + 1][1] = r3;
            }
#pragma unroll
            for (int mi = 0; mi < 4; mi++)
#pragma unroll
                for (int ni = 0; ni < 4; ni++)
                    mma8(acc[mi][ni], af[mi], bf[ni]);
        }
        __syncthreads();
    }

    // ---- epilogue 1: silu + bias -> Ms (tf32), reset acc ----
    const int lrow0 = wm * 64 + (lane >> 2);
    const int lcolw = wn * 32 + ((lane & 3) << 1);
#pragma unroll
    for (int mi = 0; mi < 4; mi++) {
        int r = lrow0 + mi * 16;
#pragma unroll
        for (int ni = 0; ni < 4; ni++) {
            int col = lcolw + ni * 8;
            float2 bb = *(const float2*)(b1 + n0 + col);
            float v0 = silu_f(acc[mi][ni][0] + bb.x);
            float v1 = silu_f(acc[mi][ni][1] + bb.y);
            float v2 = silu_f(acc[mi][ni][2] + bb.x);
            float v3 = silu_f(acc[mi][ni][3] + bb.y);
            *(uint2*)&Ms[r * MST + col]       = make_uint2(f2tf(v0), f2tf(v1));
            *(uint2*)&Ms[(r + 8) * MST + col] = make_uint2(f2tf(v2), f2tf(v3));
            acc[mi][ni][0] = 0.f; acc[mi][ni][1] = 0.f;
            acc[mi][ni][2] = 0.f; acc[mi][ni][3] = 0.f;
        }
    }

    // ---- stage 2 mainloop, K=128, A from Ms, B = w2 pair tile ----
    const uint32_t* W2 = w2T + (size_t)blockIdx.x * (128 * 128);
    for (int k0 = 0; k0 < 128; k0 += 32) {
#pragma unroll
        for (int i = 0; i < 4; i++)
            *(uint4*)&Bs[(am + 32 * i) * BST + ak] =
                *(const uint4*)(W2 + (size_t)(am + 32 * i) * 128 + k0 + ak);
        __syncthreads();
#pragma unroll
        for (int kk = 0; kk < 4; kk++) {
            uint32_t af[4][4], bf[4][2];
#pragma unroll
            for (int mi = 0; mi < 4; mi++)
                ldsm4(af[mi][0], af[mi][1], af[mi][2], af[mi][3],
                      ms_base + (((a_r + mi * 16) * MST + k0 + kk * 8 + a_q) << 2));
#pragma unroll
            for (int np = 0; np < 2; np++) {
                uint32_t r0, r1, r2, r3;
                ldsm4(r0, r1, r2, r3,
                      bs_base + (((b_r + np * 16) * BST + kk * 8 + b_q) << 2));
                bf[np * 2][0] = r0; bf[np * 2][1] = r1;
                bf[np * 2 + 1][0] = r2; bf[np * 2 + 1][1] = r3;
            }
#pragma unroll
            for (int mi = 0; mi < 4; mi++)
#pragma unroll
                for (int ni = 0; ni < 4; ni++)
                    mma8(acc[mi][ni], af[mi], bf[ni]);
        }
        __syncthreads();
    }

    // ---- epilogue 2: + b2, store f32 to ef, LN partial stats via atomics ----
#pragma unroll
    for (int mi = 0; mi < 4; mi++) {
        int r = m0 + lrow0 + mi * 16;
        float s_lo = 0.f, ss_lo = 0.f, s_hi = 0.f, ss_hi = 0.f;
#pragma unroll
        for (int ni = 0; ni < 4; ni++) {
            int col = n0 + lcolw + ni * 8;
            float2 bb = *(const float2*)(b2 + col);
            float v0 = acc[mi][ni][0] + bb.x, v1 = acc[mi][ni][1] + bb.y;
            float v2 = acc[mi][ni][2] + bb.x, v3 = acc[mi][ni][3] + bb.y;
            *(float2*)(ef + (size_t)r * Hh + col)       = make_float2(v0, v1);
            *(float2*)(ef + (size_t)(r + 8) * Hh + col) = make_float2(v2, v3);
            s_lo += v0 + v1; ss_lo += v0 * v0 + v1 * v1;
            s_hi += v2 + v3; ss_hi += v2 * v2 + v3 * v3;
        }
        // reduce across the 4 lanes of the quad (same row, different columns)
        s_lo  += __shfl_xor_sync(0xffffffffu, s_lo, 1);
        s_lo  += __shfl_xor_sync(0xffffffffu, s_lo, 2);
        ss_lo += __shfl_xor_sync(0xffffffffu, ss_lo, 1);
        ss_lo += __shfl_xor_sync(0xffffffffu, ss_lo, 2);
        s_hi  += __shfl_xor_sync(0xffffffffu, s_hi, 1);
        s_hi  += __shfl_xor_sync(0xffffffffu, s_hi, 2);
        ss_hi += __shfl_xor_sync(0xffffffffu, ss_hi, 1);
        ss_hi += __shfl_xor_sync(0xffffffffu, ss_hi, 2);
        // accumulate across wn warps + N-blocks atomically (stats zeroed in k_misc)
        if ((lane & 3) == 0) {
            atomicAdd(stats + 2 * (size_t)r,           s_lo);
            atomicAdd(stats + 2 * (size_t)r + 1,       ss_lo);
            atomicAdd(stats + 2 * (size_t)(r + 8),     s_hi);
            atomicAdd(stats + 2 * (size_t)(r + 8) + 1, ss_hi);
        }
    }
}

// LN (from stats, registers only) + agg segment-sum. One warp per edge. No ef write.
__global__ void k_aggscatter(const float* __restrict__ gam, const float* __restrict__ bet,
                             const int* __restrict__ ei) {
    int wid = blockIdx.x * (blockDim.x >> 5) + (threadIdx.x >> 5);
    int lane = threadIdx.x & 31;
    if (wid >= BE) return;
    const float* row = g_ef + (size_t)wid * Hh;
    float2 st = *(const float2*)(g_stats + 2 * (size_t)wid);
    float mu = st.x * (1.f / 256.f);
    float var = st.y * (1.f / 256.f) - mu * mu;
    float rstd = rsqrtf(var + 1e-5f);
    float4 x0 = ((const float4*)row)[lane];
    float4 x1 = ((const float4*)row)[lane + 32];
    float4 g0 = ((const float4*)gam)[lane], g1 = ((const float4*)gam)[lane + 32];
    float4 b0 = ((const float4*)bet)[lane], b1 = ((const float4*)bet)[lane + 32];
    x0.x = (x0.x - mu) * rstd * g0.x + b0.x;
    x0.y = (x0.y - mu) * rstd * g0.y + b0.y;
    x0.z = (x0.z - mu) * rstd * g0.z + b0.z;
    x0.w = (x0.w - mu) * rstd * g0.w + b0.w;
    x1.x = (x1.x - mu) * rstd * g1.x + b1.x;
    x1.y = (x1.y - mu) * rstd * g1.y + b1.y;
    x1.z = (x1.z - mu) * rstd * g1.z + b1.z;
    x1.w = (x1.w - mu) * rstd * g1.w + b1.w;
    int b = (wid >= Ee) ? 1 : 0, j = wid - b * Ee;
    int i = ei[j];
    float* arow = g_agg + ((size_t)b * Nn + i) * Hh;
    red4(arow + 4 * lane, x0);
    red4(arow + 128 + 4 * lane, x1);
}

// coord scatter: thread per edge
__global__ void k_coordscatter(const int* __restrict__ ei, float* __restrict__ outc) {
    int e = blockIdx.x * blockDim.x + threadIdx.x;
    if (e >= BE) return;
    int b = (e >= Ee) ? 1 : 0, j = e - b * Ee;
    int i = ei[j];
    float wv = g_wsc[e];
    float* dst = outc + ((size_t)b * Nn + i) * 3;
    atomicAdd(dst + 0, g_cdiff[e * 3 + 0] * wv);
    atomicAdd(dst + 1, g_cdiff[e * 3 + 1] * wv);
    atomicAdd(dst + 2, g_cdiff[e * 3 + 2] * wv);
}

// ---------------- launch ----------------
extern "C" void kernel_launch(void* const* d_in, const int* in_sizes, int n_in,
                              void* d_out, int out_size) {
    const float* h     = (const float*)d_in[0];
    const float* coord = (const float*)d_in[1];
    const int*   ei    = (const int*)d_in[2];
    const float* ew1   = (const float*)d_in[3];
    const float* eb1   = (const float*)d_in[4];
    const float* ew2   = (const float*)d_in[5];
    const float* eb2   = (const float*)d_in[6];
    const float* lng   = (const float*)d_in[7];
    const float* lnb   = (const float*)d_in[8];
    const float* nw1   = (const float*)d_in[9];
    const float* nb1   = (const float*)d_in[10];
    const float* nw2   = (const float*)d_in[11];
    const float* nb2   = (const float*)d_in[12];
    const float* cw1   = (const float*)d_in[13];
    const float* cb1   = (const float*)d_in[14];
    const float* cw2   = (const float*)d_in[15];

    float* out_h = (float*)d_out;
    float* out_c = out_h + (size_t)BNr * Ff;

    void *p_ef, *p_stats, *p_geo, *p_w1T, *p_w2T, *p_cw1T, *p_nw1T, *p_nw2T,
         *p_agg, *p_nodemid, *p_wsc;
    cudaGetSymbolAddress(&p_ef,      g_ef);
    cudaGetSymbolAddress(&p_stats,   g_stats);
    cudaGetSymbolAddress(&p_geo,     g_geo);
    cudaGetSymbolAddress(&p_w1T,     g_w1T);
    cudaGetSymbolAddress(&p_w2T,     g_w2T);
    cudaGetSymbolAddress(&p_cw1T,    g_cw1T);
    cudaGetSymbolAddress(&p_nw1T,    g_nw1T);
    cudaGetSymbolAddress(&p_nw2T,    g_nw2T);
    cudaGetSymbolAddress(&p_agg,     g_agg);
    cudaGetSymbolAddress(&p_nodemid, g_nodemid);
    cudaGetSymbolAddress(&p_wsc,     g_wsc);
    float*          efp      = (float*)p_ef;
    float*          statsp   = (float*)p_stats;
    const float*    geop     = (const float*)p_geo;
    const uint32_t* w1Tp     = (const uint32_t*)p_w1T;
    const uint32_t* w2Tp     = (const uint32_t*)p_w2T;
    const uint32_t* cw1Tp    = (const uint32_t*)p_cw1T;
    const uint32_t* nw1Tp    = (const uint32_t*)p_nw1T;
    const uint32_t* nw2Tp    = (const uint32_t*)p_nw2T;
    const float*    aggp     = (const float*)p_agg;
    float*          nodemidp = (float*)p_nodemid;
    float*          wscp     = (float*)p_wsc;

    const int smem12 = 128 * (AST + BST + MST) * 4;
    cudaFuncSetAttribute(k_gemm12, cudaFuncAttributeMaxDynamicSharedMemorySize, smem12);
    cudaFuncSetAttribute(k_gemm_t<4, 3>, cudaFuncAttributeMaxDynamicSharedMemorySize, GT_SMEM);
    cudaFuncSetAttribute(k_gemm_t<2, 2>, cudaFuncAttributeMaxDynamicSharedMemorySize, GT_SMEM);
    cudaFuncSetAttribute(k_gemm_t<3, 0>, cudaFuncAttributeMaxDynamicSharedMemorySize, GT_SMEM);

    // init + weights transform (also zeroes stats/agg/wsc)
    k_misc<<<(BNr * Hh + 255) / 256, 256>>>(coord, out_c, ew1, ew2, cw1, nw1, nw2);
    k_geo<<<BE / 256, 256>>>(coord, ei);

    // fused GEMM1+GEMM2 (+ atomic LN stats)
    k_gemm12<<<dim3(2, BE / 128), 256, smem12>>>(h, w1Tp, w2Tp, efp, ei, geop, eb1, eb2, statsp);

    // agg scatter (LN applied in registers, read-only on ef)
    k_aggscatter<<<BE / 8, 256>>>(lng, lnb, ei);

    // GEMM3 fused: wsc += silu(LN(ef) @ cw1 + cb1) . cw2   (LN inline in A path)
    k_gemm_t<4, 3><<<dim3(2, BE / 128), 256, GT_SMEM>>>(
        efp, nullptr, cw1Tp, nullptr, Hh, Hh, Hh, 0, cb1, cw2, 0, wscp, statsp, lng, lnb);

    // coord scatter
    k_coordscatter<<<BE / 256, 256>>>(ei, out_c);

    // node MLP (input concat fused via split-A)
    k_gemm_t<2, 2><<<dim3(2, BNr / 128), 256, GT_SMEM>>>(
        h, aggp, nw1Tp, nodemidp, Hh + Ff, 0, Hh + Ff, Hh, nb1, nullptr, 0, nullptr,
        nullptr, nullptr, nullptr);
    k_gemm_t<3, 0><<<dim3(1, BNr / 128), 256, GT_SMEM>>>(
        nodemidp, nullptr, nw2Tp, out_h, Hh, Hh, Hh, Ff, nb2, h, Ff, nullptr,
        nullptr, nullptr, nullptr);
}